// round 1
// baseline (speedup 1.0000x reference)
#include <cuda_runtime.h>
#include <cstdint>
#include <math.h>

#define SS 256
#define BB 64
#define HH 1024
#define VV 8192

// ---------------- scratch (device globals; no allocations allowed) ----------
__device__ float g_emb[SS * BB * HH];     // (S,B,H) embeddings + biases
__device__ float g_y[SS * BB * HH];       // (S,B,H) all hidden states
__device__ float g_wt[HH * HH];           // W_hh^T: [k][n]
__device__ float g_wih_t[VV * HH];        // W_ih^T: [v][h]
__device__ int   g_isI64;                 // x dtype flag

typedef unsigned long long u64;

__device__ __forceinline__ u64 ffma2(u64 a, u64 b, u64 c) {
    u64 d;
    asm("fma.rn.f32x2 %0, %1, %2, %3;" : "=l"(d) : "l"(a), "l"(b), "l"(c));
    return d;
}
__device__ __forceinline__ u64 pack2(float x, float y) {
    u64 r;
    asm("mov.b64 %0, {%1, %2};" : "=l"(r) : "f"(x), "f"(y));
    return r;
}
__device__ __forceinline__ float2 unpack2(u64 v) {
    float2 f;
    asm("mov.b64 {%0, %1}, %2;" : "=f"(f.x), "=f"(f.y) : "l"(v));
    return f;
}

// ---------------- dtype detection: int64 vs int32 x --------------------------
// If x is int64 (values in [0,8192)), every odd 32-bit word of the first 8192
// elements is zero. If int32, the odd words are random values — OR != 0.
__global__ void detect_k(const unsigned int* __restrict__ xw) {
    __shared__ unsigned int red[256];
    unsigned int v = 0;
    for (int i = threadIdx.x; i < 8192; i += 256) v |= xw[2 * i + 1];
    red[threadIdx.x] = v;
    __syncthreads();
    for (int st = 128; st > 0; st >>= 1) {
        if (threadIdx.x < st) red[threadIdx.x] |= red[threadIdx.x + st];
        __syncthreads();
    }
    if (threadIdx.x == 0) g_isI64 = (red[0] == 0u) ? 1 : 0;
}

// ---------------- generic transpose into device-global scratch --------------
// which==0: out = g_wt, which==1: out = g_wih_t.  out[c][r] = in[r][c]
__global__ void transpose_k(const float* __restrict__ in, int R, int C, int which) {
    __shared__ float t[32][33];
    float* out = which ? g_wih_t : g_wt;
    int c0 = blockIdx.x * 32, r0 = blockIdx.y * 32;
#pragma unroll
    for (int i = 0; i < 32; i += 8)
        t[threadIdx.y + i][threadIdx.x] =
            in[(size_t)(r0 + threadIdx.y + i) * C + c0 + threadIdx.x];
    __syncthreads();
#pragma unroll
    for (int i = 0; i < 32; i += 8)
        out[(size_t)(c0 + threadIdx.y + i) * R + r0 + threadIdx.x] =
            t[threadIdx.x][threadIdx.y + i];
}

// ---------------- embedding gather + bias fold -------------------------------
__global__ void embed_k(const void* __restrict__ xraw,
                        const float* __restrict__ b_ih,
                        const float* __restrict__ b_hh) {
    int sb = blockIdx.x;           // sb = s*BB + b
    int b = sb & (BB - 1);
    int s = sb >> 6;
    const int* xi = (const int*)xraw;
    long long pos = (long long)b * SS + s;   // x is (B,S)
    int idx = g_isI64 ? xi[2 * pos] : xi[pos];
    const float* wrow = g_wih_t + (size_t)idx * HH;
    float* erow = g_emb + (size_t)sb * HH;
    for (int h = threadIdx.x; h < HH; h += blockDim.x)
        erow[h] = wrow[h] + b_ih[h] + b_hh[h];
}

// ---------------- one recurrence step ----------------------------------------
// h_new[b][n] = tanh(emb[s][b][n] + sum_k h[b][k] * W_hh[n][k])
// grid: 64 CTAs (16 n each), 128 threads. Per-thread 2b x 4n, f32x2 packed.
__global__ void __launch_bounds__(128) rnn_step_k(int s, const float* __restrict__ state0) {
    __shared__ float sh[32][66];   // h tile transposed: [kk][b], pad 2
    __shared__ float sw[32][16];   // W^T tile: [kk][n]

    const float* hprev = (s == 0) ? state0 : (g_y + (size_t)(s - 1) * BB * HH);
    const float* emb_s = g_emb + (size_t)s * BB * HH;
    float* hout = g_y + (size_t)s * BB * HH;

    const int tid = threadIdx.x;
    const int n0 = blockIdx.x * 16;
    const int nq = tid & 3;        // 4 n-groups of 4
    const int bq = tid >> 2;       // 32 b-groups of 2
    const int kk_l = tid & 31, g = tid >> 5;   // sh loader
    const int nn = tid & 15, kw = tid >> 4;    // sw loader

    u64 a00 = 0ull, a01 = 0ull, a10 = 0ull, a11 = 0ull;

    for (int k0 = 0; k0 < HH; k0 += 32) {
#pragma unroll
        for (int i = 0; i < 16; i++) {
            int b = g * 16 + i;
            sh[kk_l][b] = hprev[b * HH + k0 + kk_l];
        }
#pragma unroll
        for (int p = 0; p < 4; p++) {
            int kk = kw + p * 8;
            sw[kk][nn] = g_wt[(size_t)(k0 + kk) * HH + n0 + nn];
        }
        __syncthreads();
#pragma unroll
        for (int kk = 0; kk < 32; kk++) {
            u64 w0 = *(const u64*)&sw[kk][nq * 4];
            u64 w1 = *(const u64*)&sw[kk][nq * 4 + 2];
            float2 hv = *(const float2*)&sh[kk][bq * 2];
            u64 h0 = pack2(hv.x, hv.x);
            u64 h1 = pack2(hv.y, hv.y);
            a00 = ffma2(h0, w0, a00);
            a01 = ffma2(h0, w1, a01);
            a10 = ffma2(h1, w0, a10);
            a11 = ffma2(h1, w1, a11);
        }
        __syncthreads();
    }

    const int b0 = bq * 2;
    const int nb = n0 + nq * 4;
    float2 r;
    r = unpack2(a00);
    hout[b0 * HH + nb]     = tanhf(r.x + emb_s[b0 * HH + nb]);
    hout[b0 * HH + nb + 1] = tanhf(r.y + emb_s[b0 * HH + nb + 1]);
    r = unpack2(a01);
    hout[b0 * HH + nb + 2] = tanhf(r.x + emb_s[b0 * HH + nb + 2]);
    hout[b0 * HH + nb + 3] = tanhf(r.y + emb_s[b0 * HH + nb + 3]);
    r = unpack2(a10);
    hout[(b0 + 1) * HH + nb]     = tanhf(r.x + emb_s[(b0 + 1) * HH + nb]);
    hout[(b0 + 1) * HH + nb + 1] = tanhf(r.y + emb_s[(b0 + 1) * HH + nb + 1]);
    r = unpack2(a11);
    hout[(b0 + 1) * HH + nb + 2] = tanhf(r.x + emb_s[(b0 + 1) * HH + nb + 2]);
    hout[(b0 + 1) * HH + nb + 3] = tanhf(r.y + emb_s[(b0 + 1) * HH + nb + 3]);
}

// ---------------- fc GEMM: out[m][v] = y[m][:] . fc_W[v][:] + fc_b[v] --------
// M=16384, N=8192, K=1024. Tile 128x128, 256 threads, per-thread 8m x 8n (f32x2).
#define FCKT 16
__global__ void __launch_bounds__(256) fc_gemm_k(const float* __restrict__ fcW,
                                                 const float* __restrict__ fcb,
                                                 float* __restrict__ out) {
    __shared__ float As[FCKT][132];
    __shared__ float Bs[FCKT][132];

    const int tid = threadIdx.x;
    const int tx = tid & 15;       // n dim: pairs at 2*tx + 32*j
    const int ty = tid >> 4;       // m dim: rows ty*8 .. ty*8+7
    const int m0 = blockIdx.y * 128, n0 = blockIdx.x * 128;
    const int lk = tid & 15, lm = tid >> 4;   // loaders

    u64 acc[8][4];
#pragma unroll
    for (int i = 0; i < 8; i++)
#pragma unroll
        for (int j = 0; j < 4; j++) acc[i][j] = 0ull;

    for (int k0 = 0; k0 < HH; k0 += FCKT) {
#pragma unroll
        for (int i = 0; i < 8; i++) {
            As[lk][lm + i * 16] = g_y[(size_t)(m0 + lm + i * 16) * HH + k0 + lk];
            Bs[lk][lm + i * 16] = fcW[(size_t)(n0 + lm + i * 16) * HH + k0 + lk];
        }
        __syncthreads();
#pragma unroll
        for (int kk = 0; kk < FCKT; kk++) {
            u64 bv[4];
#pragma unroll
            for (int j = 0; j < 4; j++)
                bv[j] = *(const u64*)&Bs[kk][tx * 2 + j * 32];
#pragma unroll
            for (int i2 = 0; i2 < 4; i2++) {
                float2 af = *(const float2*)&As[kk][ty * 8 + i2 * 2];
                u64 a0 = pack2(af.x, af.x);
                u64 a1 = pack2(af.y, af.y);
#pragma unroll
                for (int j = 0; j < 4; j++) {
                    acc[i2 * 2][j]     = ffma2(a0, bv[j], acc[i2 * 2][j]);
                    acc[i2 * 2 + 1][j] = ffma2(a1, bv[j], acc[i2 * 2 + 1][j]);
                }
            }
        }
        __syncthreads();
    }

#pragma unroll
    for (int i = 0; i < 8; i++) {
        int m = m0 + ty * 8 + i;
        float* orow = out + (size_t)m * VV + n0;
#pragma unroll
        for (int j = 0; j < 4; j++) {
            int n = 2 * tx + 32 * j;
            float2 r = unpack2(acc[i][j]);
            float2 st;
            st.x = r.x + fcb[n0 + n];
            st.y = r.y + fcb[n0 + n + 1];
            *(float2*)&orow[n] = st;
        }
    }
}

// ---------------- final state copy -------------------------------------------
__global__ void copy_state_k(float* __restrict__ dst) {
    int i = blockIdx.x * blockDim.x + threadIdx.x;
    if (i < BB * HH) dst[i] = g_y[(size_t)(SS - 1) * BB * HH + i];
}

// ---------------- launch ------------------------------------------------------
extern "C" void kernel_launch(void* const* d_in, const int* in_sizes, int n_in,
                              void* d_out, int out_size) {
    const void*  x     = d_in[0];
    const float* state = (const float*)d_in[1];   // (1,B,H)
    // W_ih = d_in[2], W_hh = d_in[3]
    const float* W_ih  = (const float*)d_in[2];
    const float* W_hh  = (const float*)d_in[3];
    const float* b_ih  = (const float*)d_in[4];
    const float* b_hh  = (const float*)d_in[5];
    const float* fc_W  = (const float*)d_in[6];
    const float* fc_b  = (const float*)d_in[7];
    float* out = (float*)d_out;

    (void)in_sizes; (void)n_in; (void)out_size;

    // 1) dtype detection for x
    detect_k<<<1, 256>>>((const unsigned int*)x);

    // 2) transposes: W_hh -> g_wt [k][n], W_ih -> g_wih_t [v][h]
    dim3 tb(32, 8);
    transpose_k<<<dim3(HH / 32, HH / 32), tb>>>(W_hh, HH, HH, 0);
    transpose_k<<<dim3(VV / 32, HH / 32), tb>>>(W_ih, HH, VV, 1);

    // 3) embeddings + folded biases
    embed_k<<<SS * BB, 256>>>(x, b_ih, b_hh);

    // 4) sequential recurrence (256 graph nodes)
    for (int s = 0; s < SS; s++)
        rnn_step_k<<<64, 128>>>(s, state);

    // 5) output projection
    fc_gemm_k<<<dim3(VV / 128, (SS * BB) / 128), 256>>>(fc_W, fc_b, out);

    // 6) final hidden state
    copy_state_k<<<64, 1024>>>(out + (size_t)SS * BB * VV);
}

// round 2
// speedup vs baseline: 1.6503x; 1.6503x over previous
#include <cuda_runtime.h>
#include <cstdint>
#include <math.h>

#define SS 256
#define BB 64
#define HH 1024
#define VV 8192

// ---------------- scratch (device globals; no allocations allowed) ----------
__device__ float g_emb[SS * BB * HH];          // (S,B,H) embeddings + biases
__device__ float g_yT[(SS + 1) * HH * BB];     // slot s: h after step s-1, layout [k][b]; slot0 = init state
__device__ float g_wih_t[VV * HH];             // W_ih^T: [v][h]
__device__ int   g_isI64;                      // x dtype flag
__device__ unsigned int g_flag[128];           // per-CTA step counters (barrier)

typedef unsigned long long u64;

__device__ __forceinline__ u64 ffma2(u64 a, u64 b, u64 c) {
    u64 d;
    asm("fma.rn.f32x2 %0, %1, %2, %3;" : "=l"(d) : "l"(a), "l"(b), "l"(c));
    return d;
}
__device__ __forceinline__ u64 pack2(float x, float y) {
    u64 r;
    asm("mov.b64 %0, {%1, %2};" : "=l"(r) : "f"(x), "f"(y));
    return r;
}
__device__ __forceinline__ float2 unpack2(u64 v) {
    float2 f;
    asm("mov.b64 {%0, %1}, %2;" : "=f"(f.x), "=f"(f.y) : "l"(v));
    return f;
}

// ---------------- dtype detection: int64 vs int32 x --------------------------
__global__ void detect_k(const unsigned int* __restrict__ xw) {
    __shared__ unsigned int red[256];
    unsigned int v = 0;
    for (int i = threadIdx.x; i < 8192; i += 256) v |= xw[2 * i + 1];
    red[threadIdx.x] = v;
    __syncthreads();
    for (int st = 128; st > 0; st >>= 1) {
        if (threadIdx.x < st) red[threadIdx.x] |= red[threadIdx.x + st];
        __syncthreads();
    }
    if (threadIdx.x == 0) g_isI64 = (red[0] == 0u) ? 1 : 0;
}

// ---------------- W_ih transpose: g_wih_t[v][h] = W_ih[h][v] -----------------
__global__ void transpose_k(const float* __restrict__ in) {
    __shared__ float t[32][33];
    const int R = HH, C = VV;
    int c0 = blockIdx.x * 32, r0 = blockIdx.y * 32;
#pragma unroll
    for (int i = 0; i < 32; i += 8)
        t[threadIdx.y + i][threadIdx.x] =
            in[(size_t)(r0 + threadIdx.y + i) * C + c0 + threadIdx.x];
    __syncthreads();
#pragma unroll
    for (int i = 0; i < 32; i += 8)
        g_wih_t[(size_t)(c0 + threadIdx.y + i) * R + r0 + threadIdx.x] =
            t[threadIdx.x][threadIdx.y + i];
}

// ---------------- init: transpose state -> yT slot 0, zero flags -------------
__global__ void st0_k(const float* __restrict__ state) {
    int j = blockIdx.x * 256 + threadIdx.x;
    if (j < BB * HH) {
        int h = j >> 6, b = j & 63;
        g_yT[j] = state[(size_t)b * HH + h];   // slot 0: [h][b]
    }
    if (j < 128) g_flag[j] = 0u;
}

// ---------------- embedding gather + bias fold --------------------------------
__global__ void embed_k(const void* __restrict__ xraw,
                        const float* __restrict__ b_ih,
                        const float* __restrict__ b_hh) {
    int sb = blockIdx.x;           // sb = s*BB + b
    int b = sb & (BB - 1);
    int s = sb >> 6;
    const int* xi = (const int*)xraw;
    long long pos = (long long)b * SS + s;    // x is (B,S)
    int idx = g_isI64 ? xi[2 * pos] : xi[pos];
    int h4 = threadIdx.x * 4;                 // 256 threads cover 1024
    float4 w  = *(const float4*)(g_wih_t + (size_t)idx * HH + h4);
    float4 bi = *(const float4*)(b_ih + h4);
    float4 bh = *(const float4*)(b_hh + h4);
    float4 o;
    o.x = w.x + bi.x + bh.x;
    o.y = w.y + bi.y + bh.y;
    o.z = w.z + bi.z + bh.z;
    o.w = w.w + bi.w + bh.w;
    *(float4*)(g_emb + (size_t)sb * HH + h4) = o;
}

// ---------------- persistent recurrence kernel --------------------------------
// 128 CTAs = 4 b-blocks(16) x 32 n-blocks(32). 256 threads.
// Thread: n = n0 + (tid&31), b-quad = bbase + ((tid>>5)&3)*4, khalf = tid>>7.
// SMEM: sW [1024][33] (132KB, resident all 256 steps), sH double-buffered
// 128-k chunks [2][128][16], sR reduction [128][4].
#define SW_FLOATS (1024 * 33)
#define SH_FLOATS (2 * 128 * 16)
#define SR_FLOATS (128 * 4)
#define RNN_SMEM_BYTES ((SW_FLOATS + SH_FLOATS + SR_FLOATS) * 4)

__global__ void __launch_bounds__(256, 1) rnn_persist_k(const float* __restrict__ W_hh) {
    extern __shared__ float sm[];
    float* sW = sm;                        // [k][33] padded
    float* sH = sm + SW_FLOATS;            // [buf][k_local][16]
    float* sR = sm + SW_FLOATS + SH_FLOATS;

    const int tid = threadIdx.x;
    const int cta = blockIdx.x;
    const int bi = cta >> 5;               // 0..3
    const int nj = cta & 31;               // 0..31
    const int n_l = tid & 31;
    const int bg = (tid >> 5) & 3;
    const int kh = tid >> 7;               // 0/1
    const int n0 = nj * 32;
    const int bbase = bi * 16;

    // Fill W slice: sW[k][r] = W_hh[n0+r][k]  (reused for all 256 steps)
    for (int idx = tid; idx < 32 * 256; idx += 256) {
        int r = idx >> 8;                  // local n, 0..31
        int kq = idx & 255;                // float4 index along k
        float4 w = *(const float4*)(W_hh + (size_t)(n0 + r) * HH + kq * 4);
        int kb = kq * 4;
        sW[(kb + 0) * 33 + r] = w.x;
        sW[(kb + 1) * 33 + r] = w.y;
        sW[(kb + 2) * 33 + r] = w.z;
        sW[(kb + 3) * 33 + r] = w.w;
    }
    __syncthreads();

    const int b0 = bbase + bg * 4;
    const int n = n0 + n_l;

    // chunk-load mapping: 512 float4 per 128k x 16b chunk, 2 per thread
    const int u0 = tid * 2;
    const int kl0 = u0 >> 2, bq0 = (u0 & 3) * 4;
    const int kl1 = (u0 + 1) >> 2, bq1 = ((u0 + 1) & 3) * 4;

    for (int s = 0; s < SS; s++) {
        const float* hsrc = g_yT + (size_t)s * (HH * BB) + bbase;  // [k][64]+boff
        float* hdst = g_yT + (size_t)(s + 1) * (HH * BB);
        const float* es = g_emb + (size_t)s * BB * HH;

        // prefetch emb for this thread's 4 outputs
        float e0 = es[(size_t)(b0 + 0) * HH + n];
        float e1 = es[(size_t)(b0 + 1) * HH + n];
        float e2 = es[(size_t)(b0 + 2) * HH + n];
        float e3 = es[(size_t)(b0 + 3) * HH + n];

        u64 acc01 = 0ull, acc23 = 0ull;

        // preload chunk 0
        float4 q0 = *(const float4*)(hsrc + (size_t)kl0 * BB + bq0);
        float4 q1 = *(const float4*)(hsrc + (size_t)kl1 * BB + bq1);
        *(float4*)&sH[kl0 * 16 + bq0] = q0;
        *(float4*)&sH[kl1 * 16 + bq1] = q1;
        __syncthreads();

        for (int c = 0; c < 8; c++) {
            const int buf = c & 1;
            if (c < 7) {
                q0 = *(const float4*)(hsrc + (size_t)((c + 1) * 128 + kl0) * BB + bq0);
                q1 = *(const float4*)(hsrc + (size_t)((c + 1) * 128 + kl1) * BB + bq1);
            }
            const float* wp = sW + (size_t)(c * 128 + (kh << 6)) * 33 + n_l;
            const float* hp = sH + (buf << 11) + ((kh << 6) << 4) + (bg << 2);
#pragma unroll 16
            for (int kk = 0; kk < 64; kk++) {
                float w = wp[kk * 33];
                ulonglong2 hv = *reinterpret_cast<const ulonglong2*>(hp + (kk << 4));
                u64 wd = pack2(w, w);
                acc01 = ffma2(hv.x, wd, acc01);
                acc23 = ffma2(hv.y, wd, acc23);
            }
            if (c < 7) {
                const int nxt = buf ^ 1;
                *(float4*)&sH[(nxt << 11) + kl0 * 16 + bq0] = q0;
                *(float4*)&sH[(nxt << 11) + kl1 * 16 + bq1] = q1;
            }
            __syncthreads();
        }

        // khalf reduction, tanh, write h_new transposed [n][b]
        if (kh == 1) {
            float2 a = unpack2(acc01), b2 = unpack2(acc23);
            *(float4*)&sR[(tid & 127) << 2] = make_float4(a.x, a.y, b2.x, b2.y);
        }
        __syncthreads();
        if (kh == 0) {
            float4 p = *(const float4*)&sR[tid << 2];
            float2 a = unpack2(acc01), b2 = unpack2(acc23);
            float4 o;
            o.x = tanhf(a.x + p.x + e0);
            o.y = tanhf(a.y + p.y + e1);
            o.z = tanhf(b2.x + p.z + e2);
            o.w = tanhf(b2.y + p.w + e3);
            *(float4*)&hdst[(size_t)n * BB + b0] = o;
        }
        __syncthreads();

        // distributed inter-CTA barrier (release/acquire)
        if (tid == 0) {
            asm volatile("st.release.gpu.global.u32 [%0], %1;"
                         :: "l"(&g_flag[cta]), "r"((unsigned)(s + 1)) : "memory");
        }
        if (tid < 128) {
            unsigned v;
            do {
                asm volatile("ld.acquire.gpu.global.u32 %0, [%1];"
                             : "=r"(v) : "l"(&g_flag[tid]) : "memory");
            } while (v < (unsigned)(s + 1));
        }
        __syncthreads();
    }
}

// ---------------- fc GEMM: out[m][v] = y[m][:].fc_W[v][:] + fc_b[v] ----------
// M=16384, N=8192, K=1024. Tile 128x128x16, 256 threads, double-buffered smem,
// register prefetch. A read from g_yT (layout [slot][k][b], slot = 1 + m/64).
__global__ void __launch_bounds__(256, 1) fc_gemm_k(const float* __restrict__ fcW,
                                                    const float* __restrict__ fcb,
                                                    float* __restrict__ out) {
    __shared__ float As[2][16][132];   // [k][m]
    __shared__ float Bs[2][16][132];   // [k][n]

    const int tid = threadIdx.x;
    const int tx = tid & 15;           // n pairs at 2*tx + 32*j
    const int ty = tid >> 4;           // m rows ty*8..+7
    const int n0 = blockIdx.x * 128, m0 = blockIdx.y * 128;

    // A loader: thread covers (k = tid>>4, m-quad = (tid&15)*4), 2 m-halves
    const int a_k = tid >> 4;          // 0..15
    const int a_m = (tid & 15) * 4;    // 0..60
    const int slot0 = 1 + (m0 >> 6);
    // B loader: thread covers (k-quad = (tid&3)*4, n = tid>>2), 2 n-halves
    const int b_k = (tid & 3) * 4;
    const int b_n = tid >> 2;          // 0..63

    u64 acc[8][4];
#pragma unroll
    for (int i = 0; i < 8; i++)
#pragma unroll
        for (int j = 0; j < 4; j++) acc[i][j] = 0ull;

    // prologue: load tile 0
    float4 pa0, pa1, pb0, pb1;
    {
        const int k0 = 0;
        pa0 = *(const float4*)(g_yT + ((size_t)(slot0 + 0) * HH + k0 + a_k) * BB + a_m);
        pa1 = *(const float4*)(g_yT + ((size_t)(slot0 + 1) * HH + k0 + a_k) * BB + a_m);
        pb0 = *(const float4*)(fcW + (size_t)(n0 + b_n) * HH + k0 + b_k);
        pb1 = *(const float4*)(fcW + (size_t)(n0 + 64 + b_n) * HH + k0 + b_k);
    }
    *(float4*)&As[0][a_k][a_m] = pa0;
    *(float4*)&As[0][a_k][64 + a_m] = pa1;
    Bs[0][b_k + 0][b_n] = pb0.x; Bs[0][b_k + 1][b_n] = pb0.y;
    Bs[0][b_k + 2][b_n] = pb0.z; Bs[0][b_k + 3][b_n] = pb0.w;
    Bs[0][b_k + 0][64 + b_n] = pb1.x; Bs[0][b_k + 1][64 + b_n] = pb1.y;
    Bs[0][b_k + 2][64 + b_n] = pb1.z; Bs[0][b_k + 3][64 + b_n] = pb1.w;
    __syncthreads();

    for (int kt = 0; kt < 64; kt++) {
        const int cur = kt & 1;
        if (kt < 63) {
            const int k0 = (kt + 1) * 16;
            pa0 = *(const float4*)(g_yT + ((size_t)(slot0 + 0) * HH + k0 + a_k) * BB + a_m);
            pa1 = *(const float4*)(g_yT + ((size_t)(slot0 + 1) * HH + k0 + a_k) * BB + a_m);
            pb0 = *(const float4*)(fcW + (size_t)(n0 + b_n) * HH + k0 + b_k);
            pb1 = *(const float4*)(fcW + (size_t)(n0 + 64 + b_n) * HH + k0 + b_k);
        }
#pragma unroll
        for (int kk = 0; kk < 16; kk++) {
            u64 bv[4];
#pragma unroll
            for (int j = 0; j < 4; j++)
                bv[j] = *(const u64*)&Bs[cur][kk][tx * 2 + j * 32];
#pragma unroll
            for (int i2 = 0; i2 < 4; i2++) {
                float2 af = *(const float2*)&As[cur][kk][ty * 8 + i2 * 2];
                u64 a0 = pack2(af.x, af.x);
                u64 a1 = pack2(af.y, af.y);
#pragma unroll
                for (int j = 0; j < 4; j++) {
                    acc[i2 * 2][j] = ffma2(a0, bv[j], acc[i2 * 2][j]);
                    acc[i2 * 2 + 1][j] = ffma2(a1, bv[j], acc[i2 * 2 + 1][j]);
                }
            }
        }
        if (kt < 63) {
            const int nxt = cur ^ 1;
            *(float4*)&As[nxt][a_k][a_m] = pa0;
            *(float4*)&As[nxt][a_k][64 + a_m] = pa1;
            Bs[nxt][b_k + 0][b_n] = pb0.x; Bs[nxt][b_k + 1][b_n] = pb0.y;
            Bs[nxt][b_k + 2][b_n] = pb0.z; Bs[nxt][b_k + 3][b_n] = pb0.w;
            Bs[nxt][b_k + 0][64 + b_n] = pb1.x; Bs[nxt][b_k + 1][64 + b_n] = pb1.y;
            Bs[nxt][b_k + 2][64 + b_n] = pb1.z; Bs[nxt][b_k + 3][64 + b_n] = pb1.w;
        }
        __syncthreads();
    }

#pragma unroll
    for (int i = 0; i < 8; i++) {
        int m = m0 + ty * 8 + i;
        float* orow = out + (size_t)m * VV + n0;
#pragma unroll
        for (int j = 0; j < 4; j++) {
            int n = 2 * tx + 32 * j;
            float2 bias = *(const float2*)&fcb[n0 + n];
            float2 r = unpack2(acc[i][j]);
            float2 st;
            st.x = r.x + bias.x;
            st.y = r.y + bias.y;
            *(float2*)&orow[n] = st;
        }
    }
}

// ---------------- final state copy: dst[b][h] = yT[256][h][b] ----------------
__global__ void copy_state_k(float* __restrict__ dst) {
    int j = blockIdx.x * 256 + threadIdx.x;
    if (j < BB * HH) {
        float v = g_yT[(size_t)SS * HH * BB + j];  // contiguous read [h][b]
        int h = j >> 6, b = j & 63;
        dst[(size_t)b * HH + h] = v;
    }
}

// ---------------- launch -------------------------------------------------------
extern "C" void kernel_launch(void* const* d_in, const int* in_sizes, int n_in,
                              void* d_out, int out_size) {
    const void*  x     = d_in[0];
    const float* state = (const float*)d_in[1];
    const float* W_ih  = (const float*)d_in[2];
    const float* W_hh  = (const float*)d_in[3];
    const float* b_ih  = (const float*)d_in[4];
    const float* b_hh  = (const float*)d_in[5];
    const float* fc_W  = (const float*)d_in[6];
    const float* fc_b  = (const float*)d_in[7];
    float* out = (float*)d_out;
    (void)in_sizes; (void)n_in; (void)out_size;

    static int smem_set = 0;
    if (!smem_set) {
        cudaFuncSetAttribute(rnn_persist_k,
                             cudaFuncAttributeMaxDynamicSharedMemorySize,
                             RNN_SMEM_BYTES);
        smem_set = 1;
    }

    // 1) x dtype detection
    detect_k<<<1, 256>>>((const unsigned int*)x);

    // 2) W_ih^T for coalesced embedding gather
    transpose_k<<<dim3(VV / 32, HH / 32), dim3(32, 8)>>>(W_ih);

    // 3) init state transpose into yT slot 0 + zero barrier flags
    st0_k<<<256, 256>>>(state);

    // 4) embeddings + folded biases
    embed_k<<<SS * BB, 256>>>(x, b_ih, b_hh);

    // 5) full recurrence, single persistent launch
    rnn_persist_k<<<128, 256, RNN_SMEM_BYTES>>>(W_hh);

    // 6) output projection
    fc_gemm_k<<<dim3(VV / 128, (SS * BB) / 128), 256>>>(fc_W, fc_b, out);

    // 7) final hidden state
    copy_state_k<<<256, 256>>>(out + (size_t)SS * BB * VV);
}

// round 6
// speedup vs baseline: 2.9178x; 1.7681x over previous
#include <cuda_runtime.h>
#include <cuda_bf16.h>
#include <cstdint>
#include <math.h>

#define SS 256
#define BB 64
#define HH 1024
#define VV 8192

// ---------------- scratch (device globals; no allocations allowed) ----------
__device__ float g_emb[SS * BB * HH];          // (S,B,H) embeddings + biases
__device__ float g_yT[(SS + 1) * HH * BB];     // slot s+1: h_s, layout [k][b]; slot0 = init
__device__ float g_wih_t[VV * HH];             // W_ih^T: [v][h]
__device__ int   g_isI64;
__device__ unsigned int g_ctr;                 // rnn inter-CTA barrier counter

// bf16 split GEMM images (K' = 3072):
//   A' [16384][3072] = [Ah | Al | Ah]
//   B' [ 8192][3072] = [Bh | Bh | Bl]
__device__ __nv_bfloat16 g_a[(size_t)16384 * 3072];
__device__ __nv_bfloat16 g_b[(size_t)8192 * 3072];

typedef unsigned long long u64;

__device__ __forceinline__ u64 ffma2(u64 a, u64 b, u64 c) {
    u64 d;
    asm("fma.rn.f32x2 %0, %1, %2, %3;" : "=l"(d) : "l"(a), "l"(b), "l"(c));
    return d;
}
__device__ __forceinline__ u64 pack2(float x, float y) {
    u64 r;
    asm("mov.b64 %0, {%1, %2};" : "=l"(r) : "f"(x), "f"(y));
    return r;
}
__device__ __forceinline__ float2 unpack2(u64 v) {
    float2 f;
    asm("mov.b64 {%0, %1}, %2;" : "=f"(f.x), "=f"(f.y) : "l"(v));
    return f;
}
__device__ __forceinline__ u64 fadd2(u64 a, u64 b) {
    return ffma2(a, pack2(1.0f, 1.0f), b);
}
__device__ __forceinline__ uint32_t smem_u32(const void* p) {
    uint32_t a;
    asm("{ .reg .u64 t; cvta.to.shared.u64 t, %1; cvt.u32.u64 %0, t; }" : "=r"(a) : "l"(p));
    return a;
}
__device__ __forceinline__ unsigned pack_bf2(float a, float b) {
    __nv_bfloat162 t = __floats2bfloat162_rn(a, b);
    unsigned u;
    memcpy(&u, &t, 4);
    return u;
}
__device__ __forceinline__ void cpasync16(uint32_t dst, const void* src) {
    asm volatile("cp.async.cg.shared.global [%0], [%1], 16;" :: "r"(dst), "l"(src) : "memory");
}
#define CP_COMMIT() asm volatile("cp.async.commit_group;" ::: "memory")
#define CP_WAIT(n)  asm volatile("cp.async.wait_group %0;" :: "n"(n) : "memory")

__device__ __forceinline__ void ldsm4(uint32_t* r, uint32_t addr) {
    asm volatile("ldmatrix.sync.aligned.m8n8.x4.shared.b16 {%0,%1,%2,%3}, [%4];"
                 : "=r"(r[0]), "=r"(r[1]), "=r"(r[2]), "=r"(r[3]) : "r"(addr));
}
__device__ __forceinline__ void mma16816(float* c, const uint32_t* a, const uint32_t* b) {
    asm volatile(
        "mma.sync.aligned.m16n8k16.row.col.f32.bf16.bf16.f32 "
        "{%0,%1,%2,%3}, {%4,%5,%6,%7}, {%8,%9}, {%0,%1,%2,%3};"
        : "+f"(c[0]), "+f"(c[1]), "+f"(c[2]), "+f"(c[3])
        : "r"(a[0]), "r"(a[1]), "r"(a[2]), "r"(a[3]), "r"(b[0]), "r"(b[1]));
}

// ---------------- dtype detection: int64 vs int32 x --------------------------
__global__ void detect_k(const unsigned int* __restrict__ xw) {
    __shared__ unsigned int red[256];
    unsigned int v = 0;
    for (int i = threadIdx.x; i < 8192; i += 256) v |= xw[2 * i + 1];
    red[threadIdx.x] = v;
    __syncthreads();
    for (int st = 128; st > 0; st >>= 1) {
        if (threadIdx.x < st) red[threadIdx.x] |= red[threadIdx.x + st];
        __syncthreads();
    }
    if (threadIdx.x == 0) g_isI64 = (red[0] == 0u) ? 1 : 0;
}

// ---------------- W_ih transpose ----------------------------------------------
__global__ void transpose_k(const float* __restrict__ in) {
    __shared__ float t[32][33];
    const int R = HH, C = VV;
    int c0 = blockIdx.x * 32, r0 = blockIdx.y * 32;
#pragma unroll
    for (int i = 0; i < 32; i += 8)
        t[threadIdx.y + i][threadIdx.x] =
            in[(size_t)(r0 + threadIdx.y + i) * C + c0 + threadIdx.x];
    __syncthreads();
#pragma unroll
    for (int i = 0; i < 32; i += 8)
        g_wih_t[(size_t)(c0 + threadIdx.y + i) * R + r0 + threadIdx.x] =
            t[threadIdx.x][threadIdx.y + i];
}

// ---------------- init: state -> yT slot 0, reset counter --------------------
__global__ void st0_k(const float* __restrict__ state) {
    int j = blockIdx.x * 256 + threadIdx.x;
    if (j < BB * HH) {
        int h = j >> 6, b = j & 63;
        g_yT[j] = state[(size_t)b * HH + h];
    }
    if (j == 0) g_ctr = 0u;
}

// ---------------- embedding gather + bias fold --------------------------------
__global__ void embed_k(const void* __restrict__ xraw,
                        const float* __restrict__ b_ih,
                        const float* __restrict__ b_hh) {
    int sb = blockIdx.x;
    int b = sb & (BB - 1);
    int s = sb >> 6;
    const int* xi = (const int*)xraw;
    long long pos = (long long)b * SS + s;
    int idx = g_isI64 ? xi[2 * pos] : xi[pos];
    int h4 = threadIdx.x * 4;
    float4 w  = *(const float4*)(g_wih_t + (size_t)idx * HH + h4);
    float4 bi = *(const float4*)(b_ih + h4);
    float4 bh = *(const float4*)(b_hh + h4);
    float4 o;
    o.x = w.x + bi.x + bh.x;
    o.y = w.y + bi.y + bh.y;
    o.z = w.z + bi.z + bh.z;
    o.w = w.w + bi.w + bh.w;
    *(float4*)(g_emb + (size_t)sb * HH + h4) = o;
}

// ---------------- persistent recurrence kernel --------------------------------
#define RNN_SW_F (32 * 1025)
#define RNN_SH_F (1024 * 16)
#define RNN_SR_B (8 * 8 * 32 * 8)
#define RNN_SMEM_BYTES (RNN_SW_F * 4 + RNN_SH_F * 4 + RNN_SR_B)

__global__ void __launch_bounds__(256, 1) rnn_persist_k(const float* __restrict__ W_hh) {
    extern __shared__ float sm[];
    float* sW = sm;                        // [n][1025]
    float* sH = sm + RNN_SW_F;             // [k][16]
    u64*   sR = (u64*)(sm + RNN_SW_F + RNN_SH_F);

    const int tid = threadIdx.x, cta = blockIdx.x;
    const int n_l = tid & 31;              // lane = local n
    const int kh  = tid >> 5;              // warp = k-slice (0..7)
    const int n0 = (cta & 31) * 32;
    const int bbase = (cta >> 5) * 16;
    const uint32_t shH = smem_u32(sH);

    // W slice load: sW[n][k] = W_hh[n0+n][k]  -- FULL 1024 k (j < 32; R4/R5 bug was j < 16)
    {
        int nr = tid >> 3, ks = tid & 7;
        const float* wsrc = W_hh + (size_t)(n0 + nr) * HH;
        float* wdst = sW + nr * 1025;
#pragma unroll
        for (int j = 0; j < 32; j++) {
            int k4 = ks + j * 8;
            float4 w = *(const float4*)(wsrc + k4 * 4);
            wdst[k4 * 4 + 0] = w.x;
            wdst[k4 * 4 + 1] = w.y;
            wdst[k4 * 4 + 2] = w.z;
            wdst[k4 * 4 + 3] = w.w;
        }
    }
    __syncthreads();

    const int rn = tid >> 3, rbp = tid & 7;
    const int eb = bbase + 2 * rbp;
    const int en = n0 + rn;

    const float* wrow = sW + n_l * 1025 + kh * 128;
    const float* hrow = sH + kh * 128 * 16;

    for (int s = 0; s < SS; s++) {
        const float* hsrc = g_yT + (size_t)s * (HH * BB) + bbase;
#pragma unroll
        for (int i = 0; i < 16; i++) {
            int id = tid + i * 256;
            int k = id >> 2, bq = id & 3;
            cpasync16(shH + (uint32_t)(k * 64 + bq * 16),
                      hsrc + (size_t)k * BB + bq * 4);
        }
        CP_COMMIT();

        const float* es = g_emb + (size_t)s * BB * HH;
        float e0 = es[(size_t)eb * HH + en];
        float e1 = es[(size_t)(eb + 1) * HH + en];

        CP_WAIT(0);
        __syncthreads();

        u64 acc[8];
#pragma unroll
        for (int bp = 0; bp < 8; bp++) acc[bp] = 0ull;

#pragma unroll 8
        for (int kk = 0; kk < 128; kk++) {
            float w = wrow[kk];
            u64 wd = pack2(w, w);
            const ulonglong2* hp = (const ulonglong2*)(hrow + kk * 16);
            ulonglong2 hA = hp[0], hB = hp[1], hC = hp[2], hD = hp[3];
            acc[0] = ffma2(hA.x, wd, acc[0]);
            acc[1] = ffma2(hA.y, wd, acc[1]);
            acc[2] = ffma2(hB.x, wd, acc[2]);
            acc[3] = ffma2(hB.y, wd, acc[3]);
            acc[4] = ffma2(hC.x, wd, acc[4]);
            acc[5] = ffma2(hC.y, wd, acc[5]);
            acc[6] = ffma2(hD.x, wd, acc[6]);
            acc[7] = ffma2(hD.y, wd, acc[7]);
        }

        u64* rp = sR + (size_t)kh * 256 + n_l;
#pragma unroll
        for (int bp = 0; bp < 8; bp++) rp[bp * 32] = acc[bp];
        __syncthreads();

        {
            const u64* q = sR + (size_t)rbp * 32 + rn;
            u64 v = q[0];
#pragma unroll
            for (int k2 = 1; k2 < 8; k2++) v = fadd2(v, q[(size_t)k2 * 256]);
            float2 f = unpack2(v);
            float2 o;
            o.x = tanhf(f.x + e0);
            o.y = tanhf(f.y + e1);
            *(float2*)(g_yT + (size_t)(s + 1) * (HH * BB) + (size_t)en * BB + eb) = o;
        }
        __syncthreads();

        if (tid == 0) {
            asm volatile("red.release.gpu.global.add.u32 [%0], %1;"
                         :: "l"(&g_ctr), "r"(1u) : "memory");
            unsigned v, target = 128u * (unsigned)(s + 1);
            do {
                asm volatile("ld.acquire.gpu.global.u32 %0, [%1];"
                             : "=r"(v) : "l"(&g_ctr) : "memory");
            } while (v < target);
        }
        __syncthreads();
    }
}

// ---------------- conv_y: g_yT -> A' = [Ah | Al | Ah] bf16 -------------------
__global__ void conv_y_k() {
    __shared__ float sm[64][65];
    const int s = blockIdx.x;              // 0..255
    const int t = threadIdx.x;             // 256
    const float* src = g_yT + (size_t)(s + 1) * HH * BB;
    const int b = t >> 2;
    const int kq = t & 3;

    for (int c = 0; c < 16; c++) {
        const float4* s4 = (const float4*)(src + (size_t)c * 64 * BB);
#pragma unroll
        for (int i = 0; i < 4; i++) {
            int idx4 = i * 256 + t;
            int kk = idx4 >> 4;
            int b4 = idx4 & 15;
            float4 v = s4[idx4];
            sm[kk][b4 * 4 + 0] = v.x;
            sm[kk][b4 * 4 + 1] = v.y;
            sm[kk][b4 * 4 + 2] = v.z;
            sm[kk][b4 * 4 + 3] = v.w;
        }
        __syncthreads();
#pragma unroll
        for (int j = 0; j < 2; j++) {
            int kbase = kq * 16 + j * 8;
            float f[8];
#pragma unroll
            for (int jj = 0; jj < 8; jj++) f[jj] = sm[kbase + jj][b];
            unsigned hx[4], lx[4];
#pragma unroll
            for (int p = 0; p < 4; p++) {
                float f0 = f[2 * p], f1 = f[2 * p + 1];
                float h0 = __bfloat162float(__float2bfloat16(f0));
                float h1 = __bfloat162float(__float2bfloat16(f1));
                hx[p] = pack_bf2(f0, f1);
                lx[p] = pack_bf2(f0 - h0, f1 - h1);
            }
            uint4 hi = make_uint4(hx[0], hx[1], hx[2], hx[3]);
            uint4 lo = make_uint4(lx[0], lx[1], lx[2], lx[3]);
            size_t m = (size_t)s * 64 + b;
            size_t off = m * 3072 + c * 64 + kbase;
            *(uint4*)(g_a + off)        = hi;   // Ah
            *(uint4*)(g_a + off + 2048) = hi;   // Ah dup (pass 3)
            *(uint4*)(g_a + off + 1024) = lo;   // Al   (pass 2)
        }
        __syncthreads();
    }
}

// ---------------- conv_w: fc_W -> B' = [Bh | Bh | Bl] bf16 -------------------
__global__ void conv_w_k(const float* __restrict__ fcW) {
    const int v = blockIdx.x;              // 8192
    const int t = threadIdx.x;             // 128
    const float4* s4 = (const float4*)(fcW + (size_t)v * HH + t * 8);
    float4 va = s4[0], vb = s4[1];
    float f[8] = {va.x, va.y, va.z, va.w, vb.x, vb.y, vb.z, vb.w};
    unsigned hx[4], lx[4];
#pragma unroll
    for (int p = 0; p < 4; p++) {
        float f0 = f[2 * p], f1 = f[2 * p + 1];
        float h0 = __bfloat162float(__float2bfloat16(f0));
        float h1 = __bfloat162float(__float2bfloat16(f1));
        hx[p] = pack_bf2(f0, f1);
        lx[p] = pack_bf2(f0 - h0, f1 - h1);
    }
    uint4 hi = make_uint4(hx[0], hx[1], hx[2], hx[3]);
    uint4 lo = make_uint4(lx[0], lx[1], lx[2], lx[3]);
    size_t off = (size_t)v * 3072 + t * 8;
    *(uint4*)(g_b + off)        = hi;   // Bh
    *(uint4*)(g_b + off + 1024) = hi;   // Bh (pass 2)
    *(uint4*)(g_b + off + 2048) = lo;   // Bl (pass 3)
}

// ---------------- fc GEMM via mma.sync bf16 ------------------------------------
// out[m][v] = A'[m][:] . B'[v][:] + fcb[v], K'=3072.
// CTA 128x128, 256 thr (8 warps: 2m x 4n), warp tile 64x32 (m16n8k16).
// 3-stage cp.async pipeline, k-chunk 32; smem rows padded to 80B.
#define FC_STAGE 20480
#define FC_SMEM  (FC_STAGE * 3)

__global__ void __launch_bounds__(256, 1) fc_mma_k(const float* __restrict__ fcb,
                                                   float* __restrict__ out) {
    extern __shared__ char dsm[];
    const int tid = threadIdx.x, lane = tid & 31, wid = tid >> 5;
    const int wm = wid & 1, wn = wid >> 1;
    const int n0 = blockIdx.x * 128, m0 = blockIdx.y * 128;
    const uint32_t sbase = smem_u32(dsm);

    float acc[4][4][4];
#pragma unroll
    for (int i = 0; i < 4; i++)
#pragma unroll
        for (int j = 0; j < 4; j++)
#pragma unroll
            for (int q = 0; q < 4; q++) acc[i][j][q] = 0.0f;

    const int lr = tid >> 2, lg = tid & 3;

#define FC_ISSUE(c, st) do {                                                    \
        uint32_t sa = sbase + (st) * FC_STAGE;                                  \
        uint32_t sb = sa + 10240;                                               \
        const __nv_bfloat16* pa = g_a + (size_t)m0 * 3072 + (c) * 32;           \
        const __nv_bfloat16* pb = g_b + (size_t)n0 * 3072 + (c) * 32;           \
        cpasync16(sa + lr * 80 + lg * 16,        pa + (size_t)lr * 3072 + lg * 8);        \
        cpasync16(sa + (lr + 64) * 80 + lg * 16, pa + (size_t)(lr + 64) * 3072 + lg * 8); \
        cpasync16(sb + lr * 80 + lg * 16,        pb + (size_t)lr * 3072 + lg * 8);        \
        cpasync16(sb + (lr + 64) * 80 + lg * 16, pb + (size_t)(lr + 64) * 3072 + lg * 8); \
    } while (0)

    FC_ISSUE(0, 0); CP_COMMIT();
    FC_ISSUE(1, 1); CP_COMMIT();

    const int arow = wm * 64 + (lane & 15);
    const int agq  = lane >> 4;
    const int brow = wn * 32 + (lane & 7) + ((lane >> 4) << 3);
    const int bgq  = (lane >> 3) & 1;

    for (int c = 0; c < 96; c++) {
        const int st = c % 3;
        CP_WAIT(1);
        __syncthreads();
        if (c + 2 < 96) FC_ISSUE(c + 2, (c + 2) % 3);
        CP_COMMIT();

        uint32_t sa = sbase + st * FC_STAGE;
        uint32_t sb = sa + 10240;
#pragma unroll
        for (int kt = 0; kt < 2; kt++) {
            uint32_t afr[4][4], bfr[2][4];
#pragma unroll
            for (int mt = 0; mt < 4; mt++)
                ldsm4(afr[mt], sa + (uint32_t)((arow + mt * 16) * 80 + (kt * 2 + agq) * 16));
#pragma unroll
            for (int bt = 0; bt < 2; bt++)
                ldsm4(bfr[bt], sb + (uint32_t)((brow + bt * 16) * 80 + (kt * 2 + bgq) * 16));
#pragma unroll
            for (int mt = 0; mt < 4; mt++)
#pragma unroll
                for (int nt = 0; nt < 4; nt++)
                    mma16816(acc[mt][nt], afr[mt], &bfr[nt >> 1][(nt & 1) * 2]);
        }
    }

#pragma unroll
    for (int mt = 0; mt < 4; mt++) {
        int row = m0 + wm * 64 + mt * 16 + (lane >> 2);
#pragma unroll
        for (int nt = 0; nt < 4; nt++) {
            int col = n0 + wn * 32 + nt * 8 + 2 * (lane & 3);
            float2 bias = *(const float2*)(fcb + col);
            float2 v0, v1;
            v0.x = acc[mt][nt][0] + bias.x;
            v0.y = acc[mt][nt][1] + bias.y;
            v1.x = acc[mt][nt][2] + bias.x;
            v1.y = acc[mt][nt][3] + bias.y;
            *(float2*)(out + (size_t)row * VV + col) = v0;
            *(float2*)(out + (size_t)(row + 8) * VV + col) = v1;
        }
    }
}

// ---------------- final state copy --------------------------------------------
__global__ void copy_state_k(float* __restrict__ dst) {
    int j = blockIdx.x * 256 + threadIdx.x;
    if (j < BB * HH) {
        float v = g_yT[(size_t)SS * HH * BB + j];
        int h = j >> 6, b = j & 63;
        dst[(size_t)b * HH + h] = v;
    }
}

// ---------------- launch --------------------------------------------------------
extern "C" void kernel_launch(void* const* d_in, const int* in_sizes, int n_in,
                              void* d_out, int out_size) {
    const void*  x     = d_in[0];
    const float* state = (const float*)d_in[1];
    const float* W_ih  = (const float*)d_in[2];
    const float* W_hh  = (const float*)d_in[3];
    const float* b_ih  = (const float*)d_in[4];
    const float* b_hh  = (const float*)d_in[5];
    const float* fc_W  = (const float*)d_in[6];
    const float* fc_b  = (const float*)d_in[7];
    float* out = (float*)d_out;
    (void)in_sizes; (void)n_in; (void)out_size;

    static int attr_set = 0;
    if (!attr_set) {
        cudaFuncSetAttribute(rnn_persist_k,
                             cudaFuncAttributeMaxDynamicSharedMemorySize,
                             RNN_SMEM_BYTES);
        cudaFuncSetAttribute(fc_mma_k,
                             cudaFuncAttributeMaxDynamicSharedMemorySize,
                             FC_SMEM);
        attr_set = 1;
    }

    detect_k<<<1, 256>>>((const unsigned int*)x);
    transpose_k<<<dim3(VV / 32, HH / 32), dim3(32, 8)>>>(W_ih);
    st0_k<<<256, 256>>>(state);
    embed_k<<<SS * BB, 256>>>(x, b_ih, b_hh);
    conv_w_k<<<VV, 128>>>(fc_W);
    rnn_persist_k<<<128, 256, RNN_SMEM_BYTES>>>(W_hh);
    conv_y_k<<<SS, 256>>>();
    fc_mma_k<<<dim3(VV / 128, (SS * BB) / 128), 256, FC_SMEM>>>(fc_b, out);
    copy_state_k<<<256, 256>>>(out + (size_t)SS * BB * VV);
}

// round 7
// speedup vs baseline: 3.2114x; 1.1006x over previous
#include <cuda_runtime.h>
#include <cuda_bf16.h>
#include <cstdint>
#include <math.h>

#define SS 256
#define BB 64
#define HH 1024
#define VV 8192

// ---------------- scratch (device globals; no allocations allowed) ----------
__device__ float g_emb[SS * BB * HH];          // (S,B,H) embeddings + biases
__device__ float g_yT[(SS + 1) * HH * BB];     // slot s+1: h_s, layout [k][b]; slot0 = init
__device__ float g_wih_t[VV * HH];             // W_ih^T: [v][h]
__device__ int   g_isI64;
__device__ unsigned int g_ctr4[4];             // per-b-group barrier counters

// bf16 split GEMM images (K' = 3072):
//   A' [16384][3072] = [Ah | Al | Ah]
//   B' [ 8192][3072] = [Bh | Bh | Bl]
__device__ __nv_bfloat16 g_a[(size_t)16384 * 3072];
__device__ __nv_bfloat16 g_b[(size_t)8192 * 3072];

typedef unsigned long long u64;

__device__ __forceinline__ u64 ffma2(u64 a, u64 b, u64 c) {
    u64 d;
    asm("fma.rn.f32x2 %0, %1, %2, %3;" : "=l"(d) : "l"(a), "l"(b), "l"(c));
    return d;
}
__device__ __forceinline__ u64 pack2(float x, float y) {
    u64 r;
    asm("mov.b64 %0, {%1, %2};" : "=l"(r) : "f"(x), "f"(y));
    return r;
}
__device__ __forceinline__ float2 unpack2(u64 v) {
    float2 f;
    asm("mov.b64 {%0, %1}, %2;" : "=f"(f.x), "=f"(f.y) : "l"(v));
    return f;
}
__device__ __forceinline__ u64 fadd2(u64 a, u64 b) {
    return ffma2(a, pack2(1.0f, 1.0f), b);
}
__device__ __forceinline__ uint32_t smem_u32(const void* p) {
    uint32_t a;
    asm("{ .reg .u64 t; cvta.to.shared.u64 t, %1; cvt.u32.u64 %0, t; }" : "=r"(a) : "l"(p));
    return a;
}
__device__ __forceinline__ unsigned pack_bf2(float a, float b) {
    __nv_bfloat162 t = __floats2bfloat162_rn(a, b);
    unsigned u;
    memcpy(&u, &t, 4);
    return u;
}
__device__ __forceinline__ void cpasync16(uint32_t dst, const void* src) {
    asm volatile("cp.async.cg.shared.global [%0], [%1], 16;" :: "r"(dst), "l"(src) : "memory");
}
#define CP_COMMIT() asm volatile("cp.async.commit_group;" ::: "memory")
#define CP_WAIT(n)  asm volatile("cp.async.wait_group %0;" :: "n"(n) : "memory")

__device__ __forceinline__ void ldsm4(uint32_t* r, uint32_t addr) {
    asm volatile("ldmatrix.sync.aligned.m8n8.x4.shared.b16 {%0,%1,%2,%3}, [%4];"
                 : "=r"(r[0]), "=r"(r[1]), "=r"(r[2]), "=r"(r[3]) : "r"(addr));
}
__device__ __forceinline__ void mma16816(float* c, const uint32_t* a, const uint32_t* b) {
    asm volatile(
        "mma.sync.aligned.m16n8k16.row.col.f32.bf16.bf16.f32 "
        "{%0,%1,%2,%3}, {%4,%5,%6,%7}, {%8,%9}, {%0,%1,%2,%3};"
        : "+f"(c[0]), "+f"(c[1]), "+f"(c[2]), "+f"(c[3])
        : "r"(a[0]), "r"(a[1]), "r"(a[2]), "r"(a[3]), "r"(b[0]), "r"(b[1]));
}

// ---------------- dtype detection: int64 vs int32 x --------------------------
__global__ void detect_k(const unsigned int* __restrict__ xw) {
    __shared__ unsigned int red[256];
    unsigned int v = 0;
    for (int i = threadIdx.x; i < 8192; i += 256) v |= xw[2 * i + 1];
    red[threadIdx.x] = v;
    __syncthreads();
    for (int st = 128; st > 0; st >>= 1) {
        if (threadIdx.x < st) red[threadIdx.x] |= red[threadIdx.x + st];
        __syncthreads();
    }
    if (threadIdx.x == 0) g_isI64 = (red[0] == 0u) ? 1 : 0;
}

// ---------------- W_ih transpose ----------------------------------------------
__global__ void transpose_k(const float* __restrict__ in) {
    __shared__ float t[32][33];
    const int R = HH, C = VV;
    int c0 = blockIdx.x * 32, r0 = blockIdx.y * 32;
#pragma unroll
    for (int i = 0; i < 32; i += 8)
        t[threadIdx.y + i][threadIdx.x] =
            in[(size_t)(r0 + threadIdx.y + i) * C + c0 + threadIdx.x];
    __syncthreads();
#pragma unroll
    for (int i = 0; i < 32; i += 8)
        g_wih_t[(size_t)(c0 + threadIdx.y + i) * R + r0 + threadIdx.x] =
            t[threadIdx.x][threadIdx.y + i];
}

// ---------------- init: state -> yT slot 0, reset counters -------------------
__global__ void st0_k(const float* __restrict__ state) {
    int j = blockIdx.x * 256 + threadIdx.x;
    if (j < BB * HH) {
        int h = j >> 6, b = j & 63;
        g_yT[j] = state[(size_t)b * HH + h];
    }
    if (j < 4) g_ctr4[j] = 0u;
}

// ---------------- embedding gather + bias fold --------------------------------
__global__ void embed_k(const void* __restrict__ xraw,
                        const float* __restrict__ b_ih,
                        const float* __restrict__ b_hh) {
    int sb = blockIdx.x;
    int b = sb & (BB - 1);
    int s = sb >> 6;
    const int* xi = (const int*)xraw;
    long long pos = (long long)b * SS + s;
    int idx = g_isI64 ? xi[2 * pos] : xi[pos];
    int h4 = threadIdx.x * 4;
    float4 w  = *(const float4*)(g_wih_t + (size_t)idx * HH + h4);
    float4 bi = *(const float4*)(b_ih + h4);
    float4 bh = *(const float4*)(b_hh + h4);
    float4 o;
    o.x = w.x + bi.x + bh.x;
    o.y = w.y + bi.y + bh.y;
    o.z = w.z + bi.z + bh.z;
    o.w = w.w + bi.w + bh.w;
    *(float4*)(g_emb + (size_t)sb * HH + h4) = o;
}

// ---------------- persistent recurrence kernel --------------------------------
// 128 CTAs = 4 b-groups(16b) x 32 n-blocks(32n), 256 threads.
// warp = k-slice (kh, 128 k); per-warp cp.async h loads (warp-local wait).
// Per-b-group barrier (32 CTAs), groups drift independently.
#define RNN_SW_F (32 * 1025)
#define RNN_SH_F (1024 * 16)
#define RNN_SR_B (8 * 8 * 32 * 8)
#define RNN_SMEM_BYTES (RNN_SW_F * 4 + RNN_SH_F * 4 + RNN_SR_B)

__global__ void __launch_bounds__(256, 1) rnn_persist_k(const float* __restrict__ W_hh) {
    extern __shared__ float sm[];
    float* sW = sm;                        // [n][1025]
    float* sH = sm + RNN_SW_F;             // [k][16]
    u64*   sR = (u64*)(sm + RNN_SW_F + RNN_SH_F);

    const int tid = threadIdx.x, cta = blockIdx.x;
    const int lane = tid & 31;             // = local n
    const int kh   = tid >> 5;             // warp = k-slice (0..7)
    const int bi = cta >> 5;               // b-group 0..3
    const int n0 = (cta & 31) * 32;
    const int bbase = bi * 16;
    const uint32_t shH = smem_u32(sH);

    // W slice load: sW[n][k] = W_hh[n0+n][k]  (full 1024 k)
    {
        int nr = tid >> 3, ks = tid & 7;
        const float* wsrc = W_hh + (size_t)(n0 + nr) * HH;
        float* wdst = sW + nr * 1025;
#pragma unroll
        for (int j = 0; j < 32; j++) {
            int k4 = ks + j * 8;
            float4 w = *(const float4*)(wsrc + k4 * 4);
            wdst[k4 * 4 + 0] = w.x;
            wdst[k4 * 4 + 1] = w.y;
            wdst[k4 * 4 + 2] = w.z;
            wdst[k4 * 4 + 3] = w.w;
        }
    }
    __syncthreads();

    const int rn = tid >> 3, rbp = tid & 7;
    const int eb = bbase + 2 * rbp;
    const int en = n0 + rn;

    const float* wrow = sW + lane * 1025 + kh * 128;
    const float* hrow = sH + kh * 128 * 16;

    for (int s = 0; s < SS; s++) {
        // per-warp h slice load: warp kh loads k in [kh*128, kh*128+128)
        const float* hsrc = g_yT + (size_t)s * (HH * BB) + bbase + (size_t)(kh * 128) * BB;
        const uint32_t sdst = shH + (uint32_t)(kh * 128) * 64;
#pragma unroll
        for (int i = 0; i < 16; i++) {
            int id = i * 32 + lane;        // 0..511
            int kl = id >> 2, bq = (id & 3) * 4;
            cpasync16(sdst + (uint32_t)(kl * 64 + bq * 4),
                      hsrc + (size_t)kl * BB + bq);
        }
        CP_COMMIT();

        // emb prefetch (overlaps cp.async)
        const float* es = g_emb + (size_t)s * BB * HH;
        float e0 = es[(size_t)eb * HH + en];
        float e1 = es[(size_t)(eb + 1) * HH + en];

        CP_WAIT(0);
        __syncwarp();

        u64 acc[8];
#pragma unroll
        for (int bp = 0; bp < 8; bp++) acc[bp] = 0ull;

#pragma unroll 8
        for (int kk = 0; kk < 128; kk++) {
            float w = wrow[kk];
            u64 wd = pack2(w, w);
            const ulonglong2* hp = (const ulonglong2*)(hrow + kk * 16);
            ulonglong2 hA = hp[0], hB = hp[1], hC = hp[2], hD = hp[3];
            acc[0] = ffma2(hA.x, wd, acc[0]);
            acc[1] = ffma2(hA.y, wd, acc[1]);
            acc[2] = ffma2(hB.x, wd, acc[2]);
            acc[3] = ffma2(hB.y, wd, acc[3]);
            acc[4] = ffma2(hC.x, wd, acc[4]);
            acc[5] = ffma2(hC.y, wd, acc[5]);
            acc[6] = ffma2(hD.x, wd, acc[6]);
            acc[7] = ffma2(hD.y, wd, acc[7]);
        }

        u64* rp = sR + (size_t)kh * 256 + lane;
#pragma unroll
        for (int bp = 0; bp < 8; bp++) rp[bp * 32] = acc[bp];
        __syncthreads();

        // reduce over kh, add emb, tanh, store transposed h_s
        {
            const u64* q = sR + (size_t)rbp * 32 + rn;
            u64 v = q[0];
#pragma unroll
            for (int k2 = 1; k2 < 8; k2++) v = fadd2(v, q[(size_t)k2 * 256]);
            float2 f = unpack2(v);
            float2 o;
            o.x = tanhf(f.x + e0);
            o.y = tanhf(f.y + e1);
            *(float2*)(g_yT + (size_t)(s + 1) * (HH * BB) + (size_t)en * BB + eb) = o;
        }
        __syncthreads();

        // per-b-group barrier: 32 CTAs
        if (tid == 0) {
            asm volatile("red.release.gpu.global.add.u32 [%0], %1;"
                         :: "l"(&g_ctr4[bi]), "r"(1u) : "memory");
            unsigned v, target = 32u * (unsigned)(s + 1);
            do {
                asm volatile("ld.acquire.gpu.global.u32 %0, [%1];"
                             : "=r"(v) : "l"(&g_ctr4[bi]) : "memory");
            } while (v < target);
        }
        __syncthreads();
    }
}

// ---------------- conv_y: g_yT -> A' = [Ah | Al | Ah] bf16 -------------------
__global__ void conv_y_k() {
    __shared__ float sm[64][65];
    const int s = blockIdx.x;              // 0..255
    const int t = threadIdx.x;             // 256
    const float* src = g_yT + (size_t)(s + 1) * HH * BB;
    const int b = t >> 2;
    const int kq = t & 3;

    for (int c = 0; c < 16; c++) {
        const float4* s4 = (const float4*)(src + (size_t)c * 64 * BB);
#pragma unroll
        for (int i = 0; i < 4; i++) {
            int idx4 = i * 256 + t;
            int kk = idx4 >> 4;
            int b4 = idx4 & 15;
            float4 v = s4[idx4];
            sm[kk][b4 * 4 + 0] = v.x;
            sm[kk][b4 * 4 + 1] = v.y;
            sm[kk][b4 * 4 + 2] = v.z;
            sm[kk][b4 * 4 + 3] = v.w;
        }
        __syncthreads();
#pragma unroll
        for (int j = 0; j < 2; j++) {
            int kbase = kq * 16 + j * 8;
            float f[8];
#pragma unroll
            for (int jj = 0; jj < 8; jj++) f[jj] = sm[kbase + jj][b];
            unsigned hx[4], lx[4];
#pragma unroll
            for (int p = 0; p < 4; p++) {
                float f0 = f[2 * p], f1 = f[2 * p + 1];
                float h0 = __bfloat162float(__float2bfloat16(f0));
                float h1 = __bfloat162float(__float2bfloat16(f1));
                hx[p] = pack_bf2(f0, f1);
                lx[p] = pack_bf2(f0 - h0, f1 - h1);
            }
            uint4 hi = make_uint4(hx[0], hx[1], hx[2], hx[3]);
            uint4 lo = make_uint4(lx[0], lx[1], lx[2], lx[3]);
            size_t m = (size_t)s * 64 + b;
            size_t off = m * 3072 + c * 64 + kbase;
            *(uint4*)(g_a + off)        = hi;   // Ah
            *(uint4*)(g_a + off + 2048) = hi;   // Ah dup (pass 3)
            *(uint4*)(g_a + off + 1024) = lo;   // Al   (pass 2)
        }
        __syncthreads();
    }
}

// ---------------- conv_w: fc_W -> B' = [Bh | Bh | Bl] bf16 -------------------
__global__ void conv_w_k(const float* __restrict__ fcW) {
    const int v = blockIdx.x;              // 8192
    const int t = threadIdx.x;             // 128
    const float4* s4 = (const float4*)(fcW + (size_t)v * HH + t * 8);
    float4 va = s4[0], vb = s4[1];
    float f[8] = {va.x, va.y, va.z, va.w, vb.x, vb.y, vb.z, vb.w};
    unsigned hx[4], lx[4];
#pragma unroll
    for (int p = 0; p < 4; p++) {
        float f0 = f[2 * p], f1 = f[2 * p + 1];
        float h0 = __bfloat162float(__float2bfloat16(f0));
        float h1 = __bfloat162float(__float2bfloat16(f1));
        hx[p] = pack_bf2(f0, f1);
        lx[p] = pack_bf2(f0 - h0, f1 - h1);
    }
    uint4 hi = make_uint4(hx[0], hx[1], hx[2], hx[3]);
    uint4 lo = make_uint4(lx[0], lx[1], lx[2], lx[3]);
    size_t off = (size_t)v * 3072 + t * 8;
    *(uint4*)(g_b + off)        = hi;   // Bh
    *(uint4*)(g_b + off + 1024) = hi;   // Bh (pass 2)
    *(uint4*)(g_b + off + 2048) = lo;   // Bl (pass 3)
}

// ---------------- fc GEMM via mma.sync bf16 ------------------------------------
// out[m][v] = A'[m][:] . B'[v][:] + fcb[v], K'=3072.
// CTA 128x256, 256 thr (8 warps: 2m x 4n), warp tile 64x64 (m16n8k16).
// 3-stage cp.async pipeline, k-chunk 32; smem rows padded to 80B.
#define FC_A_BYTES 10240                  // 128 rows * 80B
#define FC_STAGE   30720                  // + 256 rows * 80B
#define FC_SMEM    (FC_STAGE * 3)

__global__ void __launch_bounds__(256, 1) fc_mma_k(const float* __restrict__ fcb,
                                                   float* __restrict__ out) {
    extern __shared__ char dsm[];
    const int tid = threadIdx.x, lane = tid & 31, wid = tid >> 5;
    const int wm = wid & 1, wn = wid >> 1;
    const int n0 = blockIdx.x * 256, m0 = blockIdx.y * 128;
    const uint32_t sbase = smem_u32(dsm);

    float acc[4][8][4];
#pragma unroll
    for (int i = 0; i < 4; i++)
#pragma unroll
        for (int j = 0; j < 8; j++)
#pragma unroll
            for (int q = 0; q < 4; q++) acc[i][j][q] = 0.0f;

    const int lr = tid >> 2, lg = tid & 3;

#define FC_ISSUE(c, st) do {                                                              \
        uint32_t sa = sbase + (st) * FC_STAGE;                                            \
        uint32_t sb = sa + FC_A_BYTES;                                                    \
        const __nv_bfloat16* pa = g_a + (size_t)m0 * 3072 + (c) * 32;                     \
        const __nv_bfloat16* pb = g_b + (size_t)n0 * 3072 + (c) * 32;                     \
        cpasync16(sa + lr * 80 + lg * 16,          pa + (size_t)lr * 3072 + lg * 8);          \
        cpasync16(sa + (lr + 64) * 80 + lg * 16,   pa + (size_t)(lr + 64) * 3072 + lg * 8);   \
        cpasync16(sb + lr * 80 + lg * 16,          pb + (size_t)lr * 3072 + lg * 8);          \
        cpasync16(sb + (lr + 64) * 80 + lg * 16,   pb + (size_t)(lr + 64) * 3072 + lg * 8);   \
        cpasync16(sb + (lr + 128) * 80 + lg * 16,  pb + (size_t)(lr + 128) * 3072 + lg * 8);  \
        cpasync16(sb + (lr + 192) * 80 + lg * 16,  pb + (size_t)(lr + 192) * 3072 + lg * 8);  \
    } while (0)

    FC_ISSUE(0, 0); CP_COMMIT();
    FC_ISSUE(1, 1); CP_COMMIT();

    const int arow = wm * 64 + (lane & 15);
    const int agq  = lane >> 4;
    const int brow = wn * 64 + (lane & 7) + ((lane >> 4) << 3);
    const int bgq  = (lane >> 3) & 1;

    for (int c = 0; c < 96; c++) {
        const int st = c % 3;
        CP_WAIT(1);
        __syncthreads();
        if (c + 2 < 96) FC_ISSUE(c + 2, (c + 2) % 3);
        CP_COMMIT();

        uint32_t sa = sbase + st * FC_STAGE;
        uint32_t sb = sa + FC_A_BYTES;
#pragma unroll
        for (int kt = 0; kt < 2; kt++) {
            uint32_t afr[4][4], bfr[4][4];
#pragma unroll
            for (int mt = 0; mt < 4; mt++)
                ldsm4(afr[mt], sa + (uint32_t)((arow + mt * 16) * 80 + (kt * 2 + agq) * 16));
#pragma unroll
            for (int bt = 0; bt < 4; bt++)
                ldsm4(bfr[bt], sb + (uint32_t)((brow + bt * 16) * 80 + (kt * 2 + bgq) * 16));
#pragma unroll
            for (int mt = 0; mt < 4; mt++)
#pragma unroll
                for (int nt = 0; nt < 8; nt++)
                    mma16816(acc[mt][nt], afr[mt], &bfr[nt >> 1][(nt & 1) * 2]);
        }
    }

#pragma unroll
    for (int mt = 0; mt < 4; mt++) {
        int row = m0 + wm * 64 + mt * 16 + (lane >> 2);
#pragma unroll
        for (int nt = 0; nt < 8; nt++) {
            int col = n0 + wn * 64 + nt * 8 + 2 * (lane & 3);
            float2 bias = *(const float2*)(fcb + col);
            float2 v0, v1;
            v0.x = acc[mt][nt][0] + bias.x;
            v0.y = acc[mt][nt][1] + bias.y;
            v1.x = acc[mt][nt][2] + bias.x;
            v1.y = acc[mt][nt][3] + bias.y;
            *(float2*)(out + (size_t)row * VV + col) = v0;
            *(float2*)(out + (size_t)(row + 8) * VV + col) = v1;
        }
    }
}

// ---------------- final state copy --------------------------------------------
__global__ void copy_state_k(float* __restrict__ dst) {
    int j = blockIdx.x * 256 + threadIdx.x;
    if (j < BB * HH) {
        float v = g_yT[(size_t)SS * HH * BB + j];
        int h = j >> 6, b = j & 63;
        dst[(size_t)b * HH + h] = v;
    }
}

// ---------------- launch --------------------------------------------------------
extern "C" void kernel_launch(void* const* d_in, const int* in_sizes, int n_in,
                              void* d_out, int out_size) {
    const void*  x     = d_in[0];
    const float* state = (const float*)d_in[1];
    const float* W_ih  = (const float*)d_in[2];
    const float* W_hh  = (const float*)d_in[3];
    const float* b_ih  = (const float*)d_in[4];
    const float* b_hh  = (const float*)d_in[5];
    const float* fc_W  = (const float*)d_in[6];
    const float* fc_b  = (const float*)d_in[7];
    float* out = (float*)d_out;
    (void)in_sizes; (void)n_in; (void)out_size;

    static int attr_set = 0;
    if (!attr_set) {
        cudaFuncSetAttribute(rnn_persist_k,
                             cudaFuncAttributeMaxDynamicSharedMemorySize,
                             RNN_SMEM_BYTES);
        cudaFuncSetAttribute(fc_mma_k,
                             cudaFuncAttributeMaxDynamicSharedMemorySize,
                             FC_SMEM);
        attr_set = 1;
    }

    detect_k<<<1, 256>>>((const unsigned int*)x);
    transpose_k<<<dim3(VV / 32, HH / 32), dim3(32, 8)>>>(W_ih);
    st0_k<<<256, 256>>>(state);
    embed_k<<<SS * BB, 256>>>(x, b_ih, b_hh);
    conv_w_k<<<VV, 128>>>(fc_W);
    rnn_persist_k<<<128, 256, RNN_SMEM_BYTES>>>(W_hh);
    conv_y_k<<<SS, 256>>>();
    fc_mma_k<<<dim3(VV / 256, (SS * BB) / 128), 256, FC_SMEM>>>(fc_b, out);
    copy_state_k<<<256, 256>>>(out + (size_t)SS * BB * VV);
}

// round 8
// speedup vs baseline: 3.9616x; 1.2336x over previous
#include <cuda_runtime.h>
#include <cuda_fp16.h>
#include <cstdint>
#include <math.h>

#define SS 256
#define BB 64
#define HH 1024
#define VV 8192

// ---------------- scratch (device globals; no allocations allowed) ----------
__device__ float g_emb[SS * BB * HH];          // (S,B,H) embeddings + biases
__device__ float g_yT[(SS + 1) * HH * BB];     // slot s+1: h_s, layout [k][b]; slot0 = init
__device__ float g_wih_t[VV * HH];             // W_ih^T: [v][h]
__device__ int   g_isI64;
__device__ unsigned int g_ctr4[4];             // per-b-group barrier counters

// fp16 split GEMM images (K' = 2048):
//   A' [16384][2048] = [Ah | Al]   (hi + residual: exact A reconstruction)
//   B' [ 8192][2048] = [Bh | Bh]
__device__ __half g_a[(size_t)16384 * 2048];
__device__ __half g_b[(size_t)8192 * 2048];

typedef unsigned long long u64;

__device__ __forceinline__ u64 ffma2(u64 a, u64 b, u64 c) {
    u64 d;
    asm("fma.rn.f32x2 %0, %1, %2, %3;" : "=l"(d) : "l"(a), "l"(b), "l"(c));
    return d;
}
__device__ __forceinline__ u64 pack2(float x, float y) {
    u64 r;
    asm("mov.b64 %0, {%1, %2};" : "=l"(r) : "f"(x), "f"(y));
    return r;
}
__device__ __forceinline__ float2 unpack2(u64 v) {
    float2 f;
    asm("mov.b64 {%0, %1}, %2;" : "=f"(f.x), "=f"(f.y) : "l"(v));
    return f;
}
__device__ __forceinline__ u64 fadd2(u64 a, u64 b) {
    return ffma2(a, pack2(1.0f, 1.0f), b);
}
__device__ __forceinline__ uint32_t smem_u32(const void* p) {
    uint32_t a;
    asm("{ .reg .u64 t; cvta.to.shared.u64 t, %1; cvt.u32.u64 %0, t; }" : "=r"(a) : "l"(p));
    return a;
}
__device__ __forceinline__ unsigned pack_h2(float a, float b) {
    __half2 t = __floats2half2_rn(a, b);
    unsigned u;
    memcpy(&u, &t, 4);
    return u;
}
__device__ __forceinline__ void cpasync16(uint32_t dst, const void* src) {
    asm volatile("cp.async.cg.shared.global [%0], [%1], 16;" :: "r"(dst), "l"(src) : "memory");
}
#define CP_COMMIT() asm volatile("cp.async.commit_group;" ::: "memory")
#define CP_WAIT(n)  asm volatile("cp.async.wait_group %0;" :: "n"(n) : "memory")

__device__ __forceinline__ void ldsm4(uint32_t* r, uint32_t addr) {
    asm volatile("ldmatrix.sync.aligned.m8n8.x4.shared.b16 {%0,%1,%2,%3}, [%4];"
                 : "=r"(r[0]), "=r"(r[1]), "=r"(r[2]), "=r"(r[3]) : "r"(addr));
}
__device__ __forceinline__ void mma16816(float* c, const uint32_t* a, const uint32_t* b) {
    asm volatile(
        "mma.sync.aligned.m16n8k16.row.col.f32.f16.f16.f32 "
        "{%0,%1,%2,%3}, {%4,%5,%6,%7}, {%8,%9}, {%0,%1,%2,%3};"
        : "+f"(c[0]), "+f"(c[1]), "+f"(c[2]), "+f"(c[3])
        : "r"(a[0]), "r"(a[1]), "r"(a[2]), "r"(a[3]), "r"(b[0]), "r"(b[1]));
}

// ---------------- dtype detection: int64 vs int32 x --------------------------
__global__ void detect_k(const unsigned int* __restrict__ xw) {
    __shared__ unsigned int red[256];
    unsigned int v = 0;
    for (int i = threadIdx.x; i < 8192; i += 256) v |= xw[2 * i + 1];
    red[threadIdx.x] = v;
    __syncthreads();
    for (int st = 128; st > 0; st >>= 1) {
        if (threadIdx.x < st) red[threadIdx.x] |= red[threadIdx.x + st];
        __syncthreads();
    }
    if (threadIdx.x == 0) g_isI64 = (red[0] == 0u) ? 1 : 0;
}

// ---------------- W_ih transpose ----------------------------------------------
__global__ void transpose_k(const float* __restrict__ in) {
    __shared__ float t[32][33];
    const int R = HH, C = VV;
    int c0 = blockIdx.x * 32, r0 = blockIdx.y * 32;
#pragma unroll
    for (int i = 0; i < 32; i += 8)
        t[threadIdx.y + i][threadIdx.x] =
            in[(size_t)(r0 + threadIdx.y + i) * C + c0 + threadIdx.x];
    __syncthreads();
#pragma unroll
    for (int i = 0; i < 32; i += 8)
        g_wih_t[(size_t)(c0 + threadIdx.y + i) * R + r0 + threadIdx.x] =
            t[threadIdx.x][threadIdx.y + i];
}

// ---------------- init: state -> yT slot 0, reset counters -------------------
__global__ void st0_k(const float* __restrict__ state) {
    int j = blockIdx.x * 256 + threadIdx.x;
    if (j < BB * HH) {
        int h = j >> 6, b = j & 63;
        g_yT[j] = state[(size_t)b * HH + h];
    }
    if (j < 4) g_ctr4[j] = 0u;
}

// ---------------- embedding gather + bias fold --------------------------------
__global__ void embed_k(const void* __restrict__ xraw,
                        const float* __restrict__ b_ih,
                        const float* __restrict__ b_hh) {
    int sb = blockIdx.x;
    int b = sb & (BB - 1);
    int s = sb >> 6;
    const int* xi = (const int*)xraw;
    long long pos = (long long)b * SS + s;
    int idx = g_isI64 ? xi[2 * pos] : xi[pos];
    int h4 = threadIdx.x * 4;
    float4 w  = *(const float4*)(g_wih_t + (size_t)idx * HH + h4);
    float4 bi = *(const float4*)(b_ih + h4);
    float4 bh = *(const float4*)(b_hh + h4);
    float4 o;
    o.x = w.x + bi.x + bh.x;
    o.y = w.y + bi.y + bh.y;
    o.z = w.z + bi.z + bh.z;
    o.w = w.w + bi.w + bh.w;
    *(float4*)(g_emb + (size_t)sb * HH + h4) = o;
}

// ---------------- persistent recurrence kernel --------------------------------
// 128 CTAs = 4 b-groups(16b) x 32 n-blocks(32n), 256 threads. (proven R7)
#define RNN_SW_F (32 * 1025)
#define RNN_SH_F (1024 * 16)
#define RNN_SR_B (8 * 8 * 32 * 8)
#define RNN_SMEM_BYTES (RNN_SW_F * 4 + RNN_SH_F * 4 + RNN_SR_B)

__global__ void __launch_bounds__(256, 1) rnn_persist_k(const float* __restrict__ W_hh) {
    extern __shared__ float sm[];
    float* sW = sm;                        // [n][1025]
    float* sH = sm + RNN_SW_F;             // [k][16]
    u64*   sR = (u64*)(sm + RNN_SW_F + RNN_SH_F);

    const int tid = threadIdx.x, cta = blockIdx.x;
    const int lane = tid & 31;
    const int kh   = tid >> 5;
    const int bi = cta >> 5;
    const int n0 = (cta & 31) * 32;
    const int bbase = bi * 16;
    const uint32_t shH = smem_u32(sH);

    {
        int nr = tid >> 3, ks = tid & 7;
        const float* wsrc = W_hh + (size_t)(n0 + nr) * HH;
        float* wdst = sW + nr * 1025;
#pragma unroll
        for (int j = 0; j < 32; j++) {
            int k4 = ks + j * 8;
            float4 w = *(const float4*)(wsrc + k4 * 4);
            wdst[k4 * 4 + 0] = w.x;
            wdst[k4 * 4 + 1] = w.y;
            wdst[k4 * 4 + 2] = w.z;
            wdst[k4 * 4 + 3] = w.w;
        }
    }
    __syncthreads();

    const int rn = tid >> 3, rbp = tid & 7;
    const int eb = bbase + 2 * rbp;
    const int en = n0 + rn;

    const float* wrow = sW + lane * 1025 + kh * 128;
    const float* hrow = sH + kh * 128 * 16;

    for (int s = 0; s < SS; s++) {
        const float* hsrc = g_yT + (size_t)s * (HH * BB) + bbase + (size_t)(kh * 128) * BB;
        const uint32_t sdst = shH + (uint32_t)(kh * 128) * 64;
#pragma unroll
        for (int i = 0; i < 16; i++) {
            int id = i * 32 + lane;
            int kl = id >> 2, bq = (id & 3) * 4;
            cpasync16(sdst + (uint32_t)(kl * 64 + bq * 4),
                      hsrc + (size_t)kl * BB + bq);
        }
        CP_COMMIT();

        const float* es = g_emb + (size_t)s * BB * HH;
        float e0 = es[(size_t)eb * HH + en];
        float e1 = es[(size_t)(eb + 1) * HH + en];

        CP_WAIT(0);
        __syncwarp();

        u64 acc[8];
#pragma unroll
        for (int bp = 0; bp < 8; bp++) acc[bp] = 0ull;

#pragma unroll 8
        for (int kk = 0; kk < 128; kk++) {
            float w = wrow[kk];
            u64 wd = pack2(w, w);
            const ulonglong2* hp = (const ulonglong2*)(hrow + kk * 16);
            ulonglong2 hA = hp[0], hB = hp[1], hC = hp[2], hD = hp[3];
            acc[0] = ffma2(hA.x, wd, acc[0]);
            acc[1] = ffma2(hA.y, wd, acc[1]);
            acc[2] = ffma2(hB.x, wd, acc[2]);
            acc[3] = ffma2(hB.y, wd, acc[3]);
            acc[4] = ffma2(hC.x, wd, acc[4]);
            acc[5] = ffma2(hC.y, wd, acc[5]);
            acc[6] = ffma2(hD.x, wd, acc[6]);
            acc[7] = ffma2(hD.y, wd, acc[7]);
        }

        u64* rp = sR + (size_t)kh * 256 + lane;
#pragma unroll
        for (int bp = 0; bp < 8; bp++) rp[bp * 32] = acc[bp];
        __syncthreads();

        {
            const u64* q = sR + (size_t)rbp * 32 + rn;
            u64 v = q[0];
#pragma unroll
            for (int k2 = 1; k2 < 8; k2++) v = fadd2(v, q[(size_t)k2 * 256]);
            float2 f = unpack2(v);
            float2 o;
            o.x = tanhf(f.x + e0);
            o.y = tanhf(f.y + e1);
            *(float2*)(g_yT + (size_t)(s + 1) * (HH * BB) + (size_t)en * BB + eb) = o;
        }
        __syncthreads();

        if (tid == 0) {
            asm volatile("red.release.gpu.global.add.u32 [%0], %1;"
                         :: "l"(&g_ctr4[bi]), "r"(1u) : "memory");
            unsigned v, target = 32u * (unsigned)(s + 1);
            do {
                asm volatile("ld.acquire.gpu.global.u32 %0, [%1];"
                             : "=r"(v) : "l"(&g_ctr4[bi]) : "memory");
            } while (v < target);
        }
        __syncthreads();
    }
}

// ---------------- conv_y: g_yT -> A' = [Ah | Al] fp16 ------------------------
__global__ void conv_y_k() {
    __shared__ float sm[64][65];
    const int s = blockIdx.x;              // 0..255
    const int t = threadIdx.x;             // 256
    const float* src = g_yT + (size_t)(s + 1) * HH * BB;
    const int b = t >> 2;
    const int kq = t & 3;

    for (int c = 0; c < 16; c++) {
        const float4* s4 = (const float4*)(src + (size_t)c * 64 * BB);
#pragma unroll
        for (int i = 0; i < 4; i++) {
            int idx4 = i * 256 + t;
            int kk = idx4 >> 4;
            int b4 = idx4 & 15;
            float4 v = s4[idx4];
            sm[kk][b4 * 4 + 0] = v.x;
            sm[kk][b4 * 4 + 1] = v.y;
            sm[kk][b4 * 4 + 2] = v.z;
            sm[kk][b4 * 4 + 3] = v.w;
        }
        __syncthreads();
#pragma unroll
        for (int j = 0; j < 2; j++) {
            int kbase = kq * 16 + j * 8;
            float f[8];
#pragma unroll
            for (int jj = 0; jj < 8; jj++) f[jj] = sm[kbase + jj][b];
            unsigned hx[4], lx[4];
#pragma unroll
            for (int p = 0; p < 4; p++) {
                float f0 = f[2 * p], f1 = f[2 * p + 1];
                float h0 = __half2float(__float2half_rn(f0));
                float h1 = __half2float(__float2half_rn(f1));
                hx[p] = pack_h2(f0, f1);
                lx[p] = pack_h2(f0 - h0, f1 - h1);
            }
            uint4 hi = make_uint4(hx[0], hx[1], hx[2], hx[3]);
            uint4 lo = make_uint4(lx[0], lx[1], lx[2], lx[3]);
            size_t m = (size_t)s * 64 + b;
            size_t off = m * 2048 + c * 64 + kbase;
            *(uint4*)(g_a + off)        = hi;   // Ah
            *(uint4*)(g_a + off + 1024) = lo;   // Al
        }
        __syncthreads();
    }
}

// ---------------- conv_w: fc_W -> B' = [Bh | Bh] fp16 ------------------------
__global__ void conv_w_k(const float* __restrict__ fcW) {
    const int v = blockIdx.x;              // 8192
    const int t = threadIdx.x;             // 128
    const float4* s4 = (const float4*)(fcW + (size_t)v * HH + t * 8);
    float4 va = s4[0], vb = s4[1];
    float f[8] = {va.x, va.y, va.z, va.w, vb.x, vb.y, vb.z, vb.w};
    unsigned hx[4];
#pragma unroll
    for (int p = 0; p < 4; p++)
        hx[p] = pack_h2(f[2 * p], f[2 * p + 1]);
    uint4 hi = make_uint4(hx[0], hx[1], hx[2], hx[3]);
    size_t off = (size_t)v * 2048 + t * 8;
    *(uint4*)(g_b + off)        = hi;   // Bh
    *(uint4*)(g_b + off + 1024) = hi;   // Bh (pass 2)
}

// ---------------- fc GEMM via mma.sync fp16 ------------------------------------
// out[m][v] = A'[m][:] . B'[v][:] + fcb[v], K'=2048.
// CTA 128x256, 256 thr (8 warps: 2m x 4n), warp tile 64x64 (m16n8k16).
// 3-stage cp.async pipeline, k-chunk 32; smem rows padded to 80B.
#define FC_A_BYTES 10240                  // 128 rows * 80B
#define FC_STAGE   30720                  // + 256 rows * 80B
#define FC_SMEM    (FC_STAGE * 3)

__global__ void __launch_bounds__(256, 1) fc_mma_k(const float* __restrict__ fcb,
                                                   float* __restrict__ out) {
    extern __shared__ char dsm[];
    const int tid = threadIdx.x, lane = tid & 31, wid = tid >> 5;
    const int wm = wid & 1, wn = wid >> 1;
    const int n0 = blockIdx.x * 256, m0 = blockIdx.y * 128;
    const uint32_t sbase = smem_u32(dsm);

    float acc[4][8][4];
#pragma unroll
    for (int i = 0; i < 4; i++)
#pragma unroll
        for (int j = 0; j < 8; j++)
#pragma unroll
            for (int q = 0; q < 4; q++) acc[i][j][q] = 0.0f;

    const int lr = tid >> 2, lg = tid & 3;

#define FC_ISSUE(c, st) do {                                                              \
        uint32_t sa = sbase + (st) * FC_STAGE;                                            \
        uint32_t sb = sa + FC_A_BYTES;                                                    \
        const __half* pa = g_a + (size_t)m0 * 2048 + (c) * 32;                            \
        const __half* pb = g_b + (size_t)n0 * 2048 + (c) * 32;                            \
        cpasync16(sa + lr * 80 + lg * 16,          pa + (size_t)lr * 2048 + lg * 8);          \
        cpasync16(sa + (lr + 64) * 80 + lg * 16,   pa + (size_t)(lr + 64) * 2048 + lg * 8);   \
        cpasync16(sb + lr * 80 + lg * 16,          pb + (size_t)lr * 2048 + lg * 8);          \
        cpasync16(sb + (lr + 64) * 80 + lg * 16,   pb + (size_t)(lr + 64) * 2048 + lg * 8);   \
        cpasync16(sb + (lr + 128) * 80 + lg * 16,  pb + (size_t)(lr + 128) * 2048 + lg * 8);  \
        cpasync16(sb + (lr + 192) * 80 + lg * 16,  pb + (size_t)(lr + 192) * 2048 + lg * 8);  \
    } while (0)

    FC_ISSUE(0, 0); CP_COMMIT();
    FC_ISSUE(1, 1); CP_COMMIT();

    const int arow = wm * 64 + (lane & 15);
    const int agq  = lane >> 4;
    const int brow = wn * 64 + (lane & 7) + ((lane >> 4) << 3);
    const int bgq  = (lane >> 3) & 1;

    for (int c = 0; c < 64; c++) {
        const int st = c % 3;
        CP_WAIT(1);
        __syncthreads();
        if (c + 2 < 64) FC_ISSUE(c + 2, (c + 2) % 3);
        CP_COMMIT();

        uint32_t sa = sbase + st * FC_STAGE;
        uint32_t sb = sa + FC_A_BYTES;
#pragma unroll
        for (int kt = 0; kt < 2; kt++) {
            uint32_t afr[4][4], bfr[4][4];
#pragma unroll
            for (int mt = 0; mt < 4; mt++)
                ldsm4(afr[mt], sa + (uint32_t)((arow + mt * 16) * 80 + (kt * 2 + agq) * 16));
#pragma unroll
            for (int bt = 0; bt < 4; bt++)
                ldsm4(bfr[bt], sb + (uint32_t)((brow + bt * 16) * 80 + (kt * 2 + bgq) * 16));
#pragma unroll
            for (int mt = 0; mt < 4; mt++)
#pragma unroll
                for (int nt = 0; nt < 8; nt++)
                    mma16816(acc[mt][nt], afr[mt], &bfr[nt >> 1][(nt & 1) * 2]);
        }
    }

#pragma unroll
    for (int mt = 0; mt < 4; mt++) {
        int row = m0 + wm * 64 + mt * 16 + (lane >> 2);
#pragma unroll
        for (int nt = 0; nt < 8; nt++) {
            int col = n0 + wn * 64 + nt * 8 + 2 * (lane & 3);
            float2 bias = *(const float2*)(fcb + col);
            float2 v0, v1;
            v0.x = acc[mt][nt][0] + bias.x;
            v0.y = acc[mt][nt][1] + bias.y;
            v1.x = acc[mt][nt][2] + bias.x;
            v1.y = acc[mt][nt][3] + bias.y;
            *(float2*)(out + (size_t)row * VV + col) = v0;
            *(float2*)(out + (size_t)(row + 8) * VV + col) = v1;
        }
    }
}

// ---------------- final state copy --------------------------------------------
__global__ void copy_state_k(float* __restrict__ dst) {
    int j = blockIdx.x * 256 + threadIdx.x;
    if (j < BB * HH) {
        float v = g_yT[(size_t)SS * HH * BB + j];
        int h = j >> 6, b = j & 63;
        dst[(size_t)b * HH + h] = v;
    }
}

// ---------------- launch --------------------------------------------------------
extern "C" void kernel_launch(void* const* d_in, const int* in_sizes, int n_in,
                              void* d_out, int out_size) {
    const void*  x     = d_in[0];
    const float* state = (const float*)d_in[1];
    const float* W_ih  = (const float*)d_in[2];
    const float* W_hh  = (const float*)d_in[3];
    const float* b_ih  = (const float*)d_in[4];
    const float* b_hh  = (const float*)d_in[5];
    const float* fc_W  = (const float*)d_in[6];
    const float* fc_b  = (const float*)d_in[7];
    float* out = (float*)d_out;
    (void)in_sizes; (void)n_in; (void)out_size;

    static int attr_set = 0;
    if (!attr_set) {
        cudaFuncSetAttribute(rnn_persist_k,
                             cudaFuncAttributeMaxDynamicSharedMemorySize,
                             RNN_SMEM_BYTES);
        cudaFuncSetAttribute(fc_mma_k,
                             cudaFuncAttributeMaxDynamicSharedMemorySize,
                             FC_SMEM);
        attr_set = 1;
    }

    detect_k<<<1, 256>>>((const unsigned int*)x);
    transpose_k<<<dim3(VV / 32, HH / 32), dim3(32, 8)>>>(W_ih);
    st0_k<<<256, 256>>>(state);
    embed_k<<<SS * BB, 256>>>(x, b_ih, b_hh);
    conv_w_k<<<VV, 128>>>(fc_W);
    rnn_persist_k<<<128, 256, RNN_SMEM_BYTES>>>(W_hh);
    conv_y_k<<<SS, 256>>>();
    fc_mma_k<<<dim3(VV / 256, (SS * BB) / 128), 256, FC_SMEM>>>(fc_b, out);
    copy_state_k<<<256, 256>>>(out + (size_t)SS * BB * VV);
}

// round 9
// speedup vs baseline: 5.1152x; 1.2912x over previous
#include <cuda_runtime.h>
#include <cuda_fp16.h>
#include <cstdint>
#include <math.h>

#define SS 256
#define BB 64
#define HH 1024
#define VV 8192

// ---------------- scratch (device globals; no allocations allowed) ----------
__device__ float g_emb[SS * BB * HH];          // (S,B,H) embeddings + biases
__device__ float g_yT[(SS + 1) * HH * BB];     // slot s+1: h_s, layout [k][b]; slot0 = init
__device__ float g_wih_t[VV * HH];             // W_ih^T: [v][h]
__device__ int   g_isI64;
__device__ unsigned int g_ctr4[4];             // per-b-group barrier counters

// single-pass fp16 GEMM images (K' = 1024):
__device__ __half g_a[(size_t)16384 * 1024];   // A = y rounded to fp16
__device__ __half g_b[(size_t)8192 * 1024];    // B = fc_W rounded to fp16

typedef unsigned long long u64;

__device__ __forceinline__ u64 ffma2(u64 a, u64 b, u64 c) {
    u64 d;
    asm("fma.rn.f32x2 %0, %1, %2, %3;" : "=l"(d) : "l"(a), "l"(b), "l"(c));
    return d;
}
__device__ __forceinline__ u64 pack2(float x, float y) {
    u64 r;
    asm("mov.b64 %0, {%1, %2};" : "=l"(r) : "f"(x), "f"(y));
    return r;
}
__device__ __forceinline__ float2 unpack2(u64 v) {
    float2 f;
    asm("mov.b64 {%0, %1}, %2;" : "=f"(f.x), "=f"(f.y) : "l"(v));
    return f;
}
__device__ __forceinline__ u64 fadd2(u64 a, u64 b) {
    return ffma2(a, pack2(1.0f, 1.0f), b);
}
__device__ __forceinline__ uint32_t smem_u32(const void* p) {
    uint32_t a;
    asm("{ .reg .u64 t; cvta.to.shared.u64 t, %1; cvt.u32.u64 %0, t; }" : "=r"(a) : "l"(p));
    return a;
}
__device__ __forceinline__ unsigned pack_h2(float a, float b) {
    __half2 t = __floats2half2_rn(a, b);
    unsigned u;
    memcpy(&u, &t, 4);
    return u;
}
__device__ __forceinline__ void cpasync16(uint32_t dst, const void* src) {
    asm volatile("cp.async.cg.shared.global [%0], [%1], 16;" :: "r"(dst), "l"(src) : "memory");
}
#define CP_COMMIT() asm volatile("cp.async.commit_group;" ::: "memory")
#define CP_WAIT(n)  asm volatile("cp.async.wait_group %0;" :: "n"(n) : "memory")

__device__ __forceinline__ void ldsm4(uint32_t* r, uint32_t addr) {
    asm volatile("ldmatrix.sync.aligned.m8n8.x4.shared.b16 {%0,%1,%2,%3}, [%4];"
                 : "=r"(r[0]), "=r"(r[1]), "=r"(r[2]), "=r"(r[3]) : "r"(addr));
}
__device__ __forceinline__ void mma16816(float* c, const uint32_t* a, const uint32_t* b) {
    asm volatile(
        "mma.sync.aligned.m16n8k16.row.col.f32.f16.f16.f32 "
        "{%0,%1,%2,%3}, {%4,%5,%6,%7}, {%8,%9}, {%0,%1,%2,%3};"
        : "+f"(c[0]), "+f"(c[1]), "+f"(c[2]), "+f"(c[3])
        : "r"(a[0]), "r"(a[1]), "r"(a[2]), "r"(a[3]), "r"(b[0]), "r"(b[1]));
}

// ---------------- dtype detection: int64 vs int32 x --------------------------
__global__ void detect_k(const unsigned int* __restrict__ xw) {
    __shared__ unsigned int red[256];
    unsigned int v = 0;
    for (int i = threadIdx.x; i < 8192; i += 256) v |= xw[2 * i + 1];
    red[threadIdx.x] = v;
    __syncthreads();
    for (int st = 128; st > 0; st >>= 1) {
        if (threadIdx.x < st) red[threadIdx.x] |= red[threadIdx.x + st];
        __syncthreads();
    }
    if (threadIdx.x == 0) g_isI64 = (red[0] == 0u) ? 1 : 0;
}

// ---------------- W_ih transpose ----------------------------------------------
__global__ void transpose_k(const float* __restrict__ in) {
    __shared__ float t[32][33];
    const int R = HH, C = VV;
    int c0 = blockIdx.x * 32, r0 = blockIdx.y * 32;
#pragma unroll
    for (int i = 0; i < 32; i += 8)
        t[threadIdx.y + i][threadIdx.x] =
            in[(size_t)(r0 + threadIdx.y + i) * C + c0 + threadIdx.x];
    __syncthreads();
#pragma unroll
    for (int i = 0; i < 32; i += 8)
        g_wih_t[(size_t)(c0 + threadIdx.y + i) * R + r0 + threadIdx.x] =
            t[threadIdx.x][threadIdx.y + i];
}

// ---------------- init: state -> yT slot 0, reset counters -------------------
__global__ void st0_k(const float* __restrict__ state) {
    int j = blockIdx.x * 256 + threadIdx.x;
    if (j < BB * HH) {
        int h = j >> 6, b = j & 63;
        g_yT[j] = state[(size_t)b * HH + h];
    }
    if (j < 4) g_ctr4[j] = 0u;
}

// ---------------- embedding gather + bias fold --------------------------------
__global__ void embed_k(const void* __restrict__ xraw,
                        const float* __restrict__ b_ih,
                        const float* __restrict__ b_hh) {
    int sb = blockIdx.x;
    int b = sb & (BB - 1);
    int s = sb >> 6;
    const int* xi = (const int*)xraw;
    long long pos = (long long)b * SS + s;
    int idx = g_isI64 ? xi[2 * pos] : xi[pos];
    int h4 = threadIdx.x * 4;
    float4 w  = *(const float4*)(g_wih_t + (size_t)idx * HH + h4);
    float4 bi = *(const float4*)(b_ih + h4);
    float4 bh = *(const float4*)(b_hh + h4);
    float4 o;
    o.x = w.x + bi.x + bh.x;
    o.y = w.y + bi.y + bh.y;
    o.z = w.z + bi.z + bh.z;
    o.w = w.w + bi.w + bh.w;
    *(float4*)(g_emb + (size_t)sb * HH + h4) = o;
}

// ---------------- persistent recurrence kernel --------------------------------
// 128 CTAs = 4 b-groups(16b) x 32 n-blocks(32n), 256 threads. (proven R7)
#define RNN_SW_F (32 * 1025)
#define RNN_SH_F (1024 * 16)
#define RNN_SR_B (8 * 8 * 32 * 8)
#define RNN_SMEM_BYTES (RNN_SW_F * 4 + RNN_SH_F * 4 + RNN_SR_B)

__global__ void __launch_bounds__(256, 1) rnn_persist_k(const float* __restrict__ W_hh) {
    extern __shared__ float sm[];
    float* sW = sm;                        // [n][1025]
    float* sH = sm + RNN_SW_F;             // [k][16]
    u64*   sR = (u64*)(sm + RNN_SW_F + RNN_SH_F);

    const int tid = threadIdx.x, cta = blockIdx.x;
    const int lane = tid & 31;
    const int kh   = tid >> 5;
    const int bi = cta >> 5;
    const int n0 = (cta & 31) * 32;
    const int bbase = bi * 16;
    const uint32_t shH = smem_u32(sH);

    {
        int nr = tid >> 3, ks = tid & 7;
        const float* wsrc = W_hh + (size_t)(n0 + nr) * HH;
        float* wdst = sW + nr * 1025;
#pragma unroll
        for (int j = 0; j < 32; j++) {
            int k4 = ks + j * 8;
            float4 w = *(const float4*)(wsrc + k4 * 4);
            wdst[k4 * 4 + 0] = w.x;
            wdst[k4 * 4 + 1] = w.y;
            wdst[k4 * 4 + 2] = w.z;
            wdst[k4 * 4 + 3] = w.w;
        }
    }
    __syncthreads();

    const int rn = tid >> 3, rbp = tid & 7;
    const int eb = bbase + 2 * rbp;
    const int en = n0 + rn;

    const float* wrow = sW + lane * 1025 + kh * 128;
    const float* hrow = sH + kh * 128 * 16;

    for (int s = 0; s < SS; s++) {
        const float* hsrc = g_yT + (size_t)s * (HH * BB) + bbase + (size_t)(kh * 128) * BB;
        const uint32_t sdst = shH + (uint32_t)(kh * 128) * 64;
#pragma unroll
        for (int i = 0; i < 16; i++) {
            int id = i * 32 + lane;
            int kl = id >> 2, bq = (id & 3) * 4;
            cpasync16(sdst + (uint32_t)(kl * 64 + bq * 4),
                      hsrc + (size_t)kl * BB + bq);
        }
        CP_COMMIT();

        const float* es = g_emb + (size_t)s * BB * HH;
        float e0 = es[(size_t)eb * HH + en];
        float e1 = es[(size_t)(eb + 1) * HH + en];

        CP_WAIT(0);
        __syncwarp();

        u64 acc[8];
#pragma unroll
        for (int bp = 0; bp < 8; bp++) acc[bp] = 0ull;

#pragma unroll 8
        for (int kk = 0; kk < 128; kk++) {
            float w = wrow[kk];
            u64 wd = pack2(w, w);
            const ulonglong2* hp = (const ulonglong2*)(hrow + kk * 16);
            ulonglong2 hA = hp[0], hB = hp[1], hC = hp[2], hD = hp[3];
            acc[0] = ffma2(hA.x, wd, acc[0]);
            acc[1] = ffma2(hA.y, wd, acc[1]);
            acc[2] = ffma2(hB.x, wd, acc[2]);
            acc[3] = ffma2(hB.y, wd, acc[3]);
            acc[4] = ffma2(hC.x, wd, acc[4]);
            acc[5] = ffma2(hC.y, wd, acc[5]);
            acc[6] = ffma2(hD.x, wd, acc[6]);
            acc[7] = ffma2(hD.y, wd, acc[7]);
        }

        u64* rp = sR + (size_t)kh * 256 + lane;
#pragma unroll
        for (int bp = 0; bp < 8; bp++) rp[bp * 32] = acc[bp];
        __syncthreads();

        {
            const u64* q = sR + (size_t)rbp * 32 + rn;
            u64 v = q[0];
#pragma unroll
            for (int k2 = 1; k2 < 8; k2++) v = fadd2(v, q[(size_t)k2 * 256]);
            float2 f = unpack2(v);
            float2 o;
            o.x = tanhf(f.x + e0);
            o.y = tanhf(f.y + e1);
            *(float2*)(g_yT + (size_t)(s + 1) * (HH * BB) + (size_t)en * BB + eb) = o;
        }
        __syncthreads();

        if (tid == 0) {
            asm volatile("red.release.gpu.global.add.u32 [%0], %1;"
                         :: "l"(&g_ctr4[bi]), "r"(1u) : "memory");
            unsigned v, target = 32u * (unsigned)(s + 1);
            do {
                asm volatile("ld.acquire.gpu.global.u32 %0, [%1];"
                             : "=r"(v) : "l"(&g_ctr4[bi]) : "memory");
            } while (v < target);
        }
        __syncthreads();
    }
}

// ---------------- conv_y: g_yT -> A fp16 (single image) ----------------------
__global__ void conv_y_k() {
    __shared__ float sm[64][65];
    const int s = blockIdx.x;              // 0..255
    const int t = threadIdx.x;             // 256
    const float* src = g_yT + (size_t)(s + 1) * HH * BB;
    const int b = t >> 2;
    const int kq = t & 3;

    for (int c = 0; c < 16; c++) {
        const float4* s4 = (const float4*)(src + (size_t)c * 64 * BB);
#pragma unroll
        for (int i = 0; i < 4; i++) {
            int idx4 = i * 256 + t;
            int kk = idx4 >> 4;
            int b4 = idx4 & 15;
            float4 v = s4[idx4];
            sm[kk][b4 * 4 + 0] = v.x;
            sm[kk][b4 * 4 + 1] = v.y;
            sm[kk][b4 * 4 + 2] = v.z;
            sm[kk][b4 * 4 + 3] = v.w;
        }
        __syncthreads();
#pragma unroll
        for (int j = 0; j < 2; j++) {
            int kbase = kq * 16 + j * 8;
            float f[8];
#pragma unroll
            for (int jj = 0; jj < 8; jj++) f[jj] = sm[kbase + jj][b];
            unsigned hx[4];
#pragma unroll
            for (int p = 0; p < 4; p++)
                hx[p] = pack_h2(f[2 * p], f[2 * p + 1]);
            size_t m = (size_t)s * 64 + b;
            *(uint4*)(g_a + m * 1024 + c * 64 + kbase) = make_uint4(hx[0], hx[1], hx[2], hx[3]);
        }
        __syncthreads();
    }
}

// ---------------- conv_w: fc_W -> B fp16 (single image) ----------------------
__global__ void conv_w_k(const float* __restrict__ fcW) {
    const int v = blockIdx.x;              // 8192
    const int t = threadIdx.x;             // 128
    const float4* s4 = (const float4*)(fcW + (size_t)v * HH + t * 8);
    float4 va = s4[0], vb = s4[1];
    float f[8] = {va.x, va.y, va.z, va.w, vb.x, vb.y, vb.z, vb.w};
    unsigned hx[4];
#pragma unroll
    for (int p = 0; p < 4; p++)
        hx[p] = pack_h2(f[2 * p], f[2 * p + 1]);
    *(uint4*)(g_b + (size_t)v * 1024 + t * 8) = make_uint4(hx[0], hx[1], hx[2], hx[3]);
}

// ---------------- fc GEMM via mma.sync fp16, K'=1024 --------------------------
// CTA 128x256, 256 thr (8 warps: 2m x 4n), warp tile 64x64 (m16n8k16).
// 3-stage cp.async pipeline, k-chunk 32; smem rows padded to 80B.
#define FC_A_BYTES 10240                  // 128 rows * 80B
#define FC_STAGE   30720                  // + 256 rows * 80B
#define FC_SMEM    (FC_STAGE * 3)

__global__ void __launch_bounds__(256, 1) fc_mma_k(const float* __restrict__ fcb,
                                                   float* __restrict__ out) {
    extern __shared__ char dsm[];
    const int tid = threadIdx.x, lane = tid & 31, wid = tid >> 5;
    const int wm = wid & 1, wn = wid >> 1;
    const int n0 = blockIdx.x * 256, m0 = blockIdx.y * 128;
    const uint32_t sbase = smem_u32(dsm);

    float acc[4][8][4];
#pragma unroll
    for (int i = 0; i < 4; i++)
#pragma unroll
        for (int j = 0; j < 8; j++)
#pragma unroll
            for (int q = 0; q < 4; q++) acc[i][j][q] = 0.0f;

    const int lr = tid >> 2, lg = tid & 3;

#define FC_ISSUE(c, st) do {                                                              \
        uint32_t sa = sbase + (st) * FC_STAGE;                                            \
        uint32_t sb = sa + FC_A_BYTES;                                                    \
        const __half* pa = g_a + (size_t)m0 * 1024 + (c) * 32;                            \
        const __half* pb = g_b + (size_t)n0 * 1024 + (c) * 32;                            \
        cpasync16(sa + lr * 80 + lg * 16,          pa + (size_t)lr * 1024 + lg * 8);          \
        cpasync16(sa + (lr + 64) * 80 + lg * 16,   pa + (size_t)(lr + 64) * 1024 + lg * 8);   \
        cpasync16(sb + lr * 80 + lg * 16,          pb + (size_t)lr * 1024 + lg * 8);          \
        cpasync16(sb + (lr + 64) * 80 + lg * 16,   pb + (size_t)(lr + 64) * 1024 + lg * 8);   \
        cpasync16(sb + (lr + 128) * 80 + lg * 16,  pb + (size_t)(lr + 128) * 1024 + lg * 8);  \
        cpasync16(sb + (lr + 192) * 80 + lg * 16,  pb + (size_t)(lr + 192) * 1024 + lg * 8);  \
    } while (0)

    FC_ISSUE(0, 0); CP_COMMIT();
    FC_ISSUE(1, 1); CP_COMMIT();

    const int arow = wm * 64 + (lane & 15);
    const int agq  = lane >> 4;
    const int brow = wn * 64 + (lane & 7) + ((lane >> 4) << 3);
    const int bgq  = (lane >> 3) & 1;

    for (int c = 0; c < 32; c++) {
        const int st = c % 3;
        CP_WAIT(1);
        __syncthreads();
        if (c + 2 < 32) FC_ISSUE(c + 2, (c + 2) % 3);
        CP_COMMIT();

        uint32_t sa = sbase + st * FC_STAGE;
        uint32_t sb = sa + FC_A_BYTES;
#pragma unroll
        for (int kt = 0; kt < 2; kt++) {
            uint32_t afr[4][4], bfr[4][4];
#pragma unroll
            for (int mt = 0; mt < 4; mt++)
                ldsm4(afr[mt], sa + (uint32_t)((arow + mt * 16) * 80 + (kt * 2 + agq) * 16));
#pragma unroll
            for (int bt = 0; bt < 4; bt++)
                ldsm4(bfr[bt], sb + (uint32_t)((brow + bt * 16) * 80 + (kt * 2 + bgq) * 16));
#pragma unroll
            for (int mt = 0; mt < 4; mt++)
#pragma unroll
                for (int nt = 0; nt < 8; nt++)
                    mma16816(acc[mt][nt], afr[mt], &bfr[nt >> 1][(nt & 1) * 2]);
        }
    }

#pragma unroll
    for (int mt = 0; mt < 4; mt++) {
        int row = m0 + wm * 64 + mt * 16 + (lane >> 2);
#pragma unroll
        for (int nt = 0; nt < 8; nt++) {
            int col = n0 + wn * 64 + nt * 8 + 2 * (lane & 3);
            float2 bias = *(const float2*)(fcb + col);
            float2 v0, v1;
            v0.x = acc[mt][nt][0] + bias.x;
            v0.y = acc[mt][nt][1] + bias.y;
            v1.x = acc[mt][nt][2] + bias.x;
            v1.y = acc[mt][nt][3] + bias.y;
            *(float2*)(out + (size_t)row * VV + col) = v0;
            *(float2*)(out + (size_t)(row + 8) * VV + col) = v1;
        }
    }
}

// ---------------- final state copy --------------------------------------------
__global__ void copy_state_k(float* __restrict__ dst) {
    int j = blockIdx.x * 256 + threadIdx.x;
    if (j < BB * HH) {
        float v = g_yT[(size_t)SS * HH * BB + j];
        int h = j >> 6, b = j & 63;
        dst[(size_t)b * HH + h] = v;
    }
}

// ---------------- launch --------------------------------------------------------
extern "C" void kernel_launch(void* const* d_in, const int* in_sizes, int n_in,
                              void* d_out, int out_size) {
    const void*  x     = d_in[0];
    const float* state = (const float*)d_in[1];
    const float* W_ih  = (const float*)d_in[2];
    const float* W_hh  = (const float*)d_in[3];
    const float* b_ih  = (const float*)d_in[4];
    const float* b_hh  = (const float*)d_in[5];
    const float* fc_W  = (const float*)d_in[6];
    const float* fc_b  = (const float*)d_in[7];
    float* out = (float*)d_out;
    (void)in_sizes; (void)n_in; (void)out_size;

    static int attr_set = 0;
    if (!attr_set) {
        cudaFuncSetAttribute(rnn_persist_k,
                             cudaFuncAttributeMaxDynamicSharedMemorySize,
                             RNN_SMEM_BYTES);
        cudaFuncSetAttribute(fc_mma_k,
                             cudaFuncAttributeMaxDynamicSharedMemorySize,
                             FC_SMEM);
        attr_set = 1;
    }

    detect_k<<<1, 256>>>((const unsigned int*)x);
    transpose_k<<<dim3(VV / 32, HH / 32), dim3(32, 8)>>>(W_ih);
    st0_k<<<256, 256>>>(state);
    embed_k<<<SS * BB, 256>>>(x, b_ih, b_hh);
    conv_w_k<<<VV, 128>>>(fc_W);
    rnn_persist_k<<<128, 256, RNN_SMEM_BYTES>>>(W_hh);
    conv_y_k<<<SS, 256>>>();
    fc_mma_k<<<dim3(VV / 256, (SS * BB) / 128), 256, FC_SMEM>>>(fc_b, out);
    copy_state_k<<<256, 256>>>(out + (size_t)SS * BB * VV);
}